// round 1
// baseline (speedup 1.0000x reference)
#include <cuda_runtime.h>
#include <stdint.h>
#include <math.h>

#define FEAT     256
#define MAX_DEG  128
#define BATCH    1024
#define NS0      10
#define NS1      25
#define M1SZ     (BATCH * NS0)   /* 10240 */

// ---------------- scratch (static device allocations, allowed) ----------------
__device__ float g_H1[M1SZ * FEAT];   // features[s1]            [10240,256]
__device__ float g_M1[M1SZ * FEAT];   // mean of 25 hop-2 rows   [10240,256]
__device__ float g_C1[M1SZ * FEAT];   // layer0 hop1 output      [10240,256]
__device__ float g_H0[BATCH * FEAT];  // features[node_ids]      [1024,256]
__device__ float g_M0[BATCH * FEAT];  // mean of 10 H1 rows      [1024,256]
__device__ float g_C0[BATCH * FEAT];  // layer0 hop0 output      [1024,256]
__device__ float g_M2[BATCH * FEAT];  // mean of 10 C1 rows      [1024,256]
__device__ float g_Hf[BATCH * FEAT];  // layer1 output           [1024,256]

// ---------------- threefry2x32 (JAX-compatible, 20 rounds) ----------------
__host__ __device__ __forceinline__ uint32_t rotl32_(uint32_t x, int r) {
    return (x << r) | (x >> (32 - r));
}

__host__ __device__ inline void tf2x32(uint32_t k0, uint32_t k1,
                                       uint32_t x0, uint32_t x1,
                                       uint32_t &o0, uint32_t &o1) {
    uint32_t ks2 = k0 ^ k1 ^ 0x1BD11BDAu;
    x0 += k0; x1 += k1;
#define TFR(r) { x0 += x1; x1 = rotl32_(x1, (r)); x1 ^= x0; }
    TFR(13) TFR(15) TFR(26) TFR(6)
    x0 += k1;  x1 += ks2 + 1u;
    TFR(17) TFR(29) TFR(16) TFR(24)
    x0 += ks2; x1 += k0 + 2u;
    TFR(13) TFR(15) TFR(26) TFR(6)
    x0 += k0;  x1 += k1 + 3u;
    TFR(17) TFR(29) TFR(16) TFR(24)
    x0 += k1;  x1 += ks2 + 4u;
    TFR(13) TFR(15) TFR(26) TFR(6)
    x0 += ks2; x1 += k0 + 5u;
#undef TFR
    o0 = x0; o1 = x1;
}

// jax partitionable random_bits (32-bit): bits[t] = y0 ^ y1 of block(key,(0,t));
// randint span=128 -> col = bits & 127
__device__ __forceinline__ int rnd_col(uint32_t k0, uint32_t k1, uint32_t t) {
    uint32_t a, b;
    tf2x32(k0, k1, 0u, t, a, b);
    return (int)((a ^ b) & (uint32_t)(MAX_DEG - 1));
}

// ---------------- fused sample + gather + mean for hop 1 ----------------
// block j in [0,10240): computes s1[j], its 25 hop-2 samples, then
// H1[j,:] = features[s1[j]] and M1[j,:] = mean_25 features[s2].
__global__ void __launch_bounds__(FEAT)
k_hop1(const float* __restrict__ feat, const int* __restrict__ adj,
       const int* __restrict__ node_ids,
       uint32_t l0a, uint32_t l0b, uint32_t l1a, uint32_t l1b) {
    const int j = blockIdx.x;
    const int tid = threadIdx.x;
    __shared__ int s2s[NS1];
    __shared__ int s1sh;
    if (tid == 0) {
        int c0 = rnd_col(l0a, l0b, (uint32_t)j);
        s1sh = adj[(size_t)node_ids[j / NS0] * MAX_DEG + c0];
    }
    __syncthreads();
    const int s1v = s1sh;
    if (tid < NS1) {
        int c1 = rnd_col(l1a, l1b, (uint32_t)(j * NS1 + tid));
        s2s[tid] = adj[(size_t)s1v * MAX_DEG + c1];
    }
    __syncthreads();
    g_H1[(size_t)j * FEAT + tid] = feat[(size_t)s1v * FEAT + tid];
    float acc = 0.f;
#pragma unroll
    for (int s = 0; s < NS1; s++)
        acc += feat[(size_t)s2s[s] * FEAT + tid];
    g_M1[(size_t)j * FEAT + tid] = acc * (1.0f / NS1);
}

// hop 0 prep: H0 = features[node_ids], M0 = group-mean(10) of H1
__global__ void __launch_bounds__(FEAT)
k_hop0(const float* __restrict__ feat, const int* __restrict__ node_ids) {
    const int i = blockIdx.x, tid = threadIdx.x;
    g_H0[(size_t)i * FEAT + tid] = feat[(size_t)node_ids[i] * FEAT + tid];
    float acc = 0.f;
#pragma unroll
    for (int s = 0; s < NS0; s++)
        acc += g_H1[(size_t)(i * NS0 + s) * FEAT + tid];
    g_M0[(size_t)i * FEAT + tid] = acc * (1.0f / NS0);
}

__global__ void __launch_bounds__(FEAT)
k_mean10(const float* __restrict__ src, float* __restrict__ dst) {
    const int i = blockIdx.x, tid = threadIdx.x;
    float acc = 0.f;
#pragma unroll
    for (int s = 0; s < NS0; s++)
        acc += src[(size_t)(i * NS0 + s) * FEAT + tid];
    dst[(size_t)i * FEAT + tid] = acc * (1.0f / NS0);
}

// ---------------- GEMM: C[:,0:128]=relu(A0@W0), C[:,128:256]=relu(A1@W1) ----
// K=256, N per half = 128. 128 threads, TMx8 microtile, BM = 8*TM rows/block.
template<int TM>
__global__ void __launch_bounds__(128)
k_gemm_relu(const float* __restrict__ A0, const float* __restrict__ A1,
            const float* __restrict__ W0, const float* __restrict__ W1,
            float* __restrict__ C) {
    constexpr int BM = TM * 8;
    const float* __restrict__ A = blockIdx.y ? A1 : A0;
    const float* __restrict__ W = blockIdx.y ? W1 : W0;
    const int colOff = blockIdx.y * 128;
    const int m0 = blockIdx.x * BM;
    __shared__ float As[16][BM];
    __shared__ float Bs[16][128];
    const int tid = threadIdx.x;
    const int tn = tid & 15;   // 16 col-threads * 8 cols = 128
    const int tm = tid >> 4;   // 8 row-threads * TM rows = BM
    float acc[TM][8];
#pragma unroll
    for (int x = 0; x < TM; x++)
#pragma unroll
        for (int y = 0; y < 8; y++) acc[x][y] = 0.f;

    for (int k0 = 0; k0 < FEAT; k0 += 16) {
        constexpr int NF4A = BM * 4;  // float4 count of A tile
#pragma unroll
        for (int i = 0; i < (NF4A + 127) / 128; i++) {
            int idx = i * 128 + tid;
            if ((NF4A % 128 == 0) || (idx < NF4A)) {
                int r = idx >> 2, q = idx & 3;
                float4 v = *reinterpret_cast<const float4*>(
                    A + (size_t)(m0 + r) * FEAT + k0 + q * 4);
                As[q * 4 + 0][r] = v.x; As[q * 4 + 1][r] = v.y;
                As[q * 4 + 2][r] = v.z; As[q * 4 + 3][r] = v.w;
            }
        }
#pragma unroll
        for (int i = 0; i < 4; i++) {
            int idx = i * 128 + tid;
            int r = idx >> 5, c = (idx & 31) * 4;
            *reinterpret_cast<float4*>(&Bs[r][c]) =
                *reinterpret_cast<const float4*>(W + (size_t)(k0 + r) * 128 + c);
        }
        __syncthreads();
#pragma unroll
        for (int kk = 0; kk < 16; kk++) {
            float a[TM], b[8];
#pragma unroll
            for (int x = 0; x < TM; x++) a[x] = As[kk][tm * TM + x];
#pragma unroll
            for (int y = 0; y < 8; y++) b[y] = Bs[kk][tn * 8 + y];
#pragma unroll
            for (int x = 0; x < TM; x++)
#pragma unroll
                for (int y = 0; y < 8; y++)
                    acc[x][y] = fmaf(a[x], b[y], acc[x][y]);
        }
        __syncthreads();
    }
#pragma unroll
    for (int x = 0; x < TM; x++) {
        const int m = m0 + tm * TM + x;
        float4 v0 = make_float4(fmaxf(acc[x][0], 0.f), fmaxf(acc[x][1], 0.f),
                                fmaxf(acc[x][2], 0.f), fmaxf(acc[x][3], 0.f));
        float4 v1 = make_float4(fmaxf(acc[x][4], 0.f), fmaxf(acc[x][5], 0.f),
                                fmaxf(acc[x][6], 0.f), fmaxf(acc[x][7], 0.f));
        float* p = C + (size_t)m * FEAT + colOff + tn * 8;
        *reinterpret_cast<float4*>(p) = v0;
        *reinterpret_cast<float4*>(p + 4) = v1;
    }
}

// ---------------- final: l2-normalize rows of Hf, dot with w_out ----------
__global__ void __launch_bounds__(FEAT)
k_final(const float* __restrict__ w_out, const float* __restrict__ b_out,
        float* __restrict__ out) {
    const int i = blockIdx.x, tid = threadIdx.x;
    float h = g_Hf[(size_t)i * FEAT + tid];
    float ss = h * h;
    float dv = h * w_out[tid];
#pragma unroll
    for (int off = 16; off > 0; off >>= 1) {
        ss += __shfl_down_sync(0xffffffffu, ss, off);
        dv += __shfl_down_sync(0xffffffffu, dv, off);
    }
    __shared__ float rs[8], rd[8];
    if ((tid & 31) == 0) { rs[tid >> 5] = ss; rd[tid >> 5] = dv; }
    __syncthreads();
    if (tid == 0) {
        float S = 0.f, D = 0.f;
#pragma unroll
        for (int w = 0; w < 8; w++) { S += rs[w]; D += rd[w]; }
        out[i] = D / sqrtf(fmaxf(S, 1e-12f)) + b_out[0];
    }
}

// ---------------- launch ----------------
extern "C" void kernel_launch(void* const* d_in, const int* in_sizes, int n_in,
                              void* d_out, int out_size) {
    const float* feat     = (const float*)d_in[0];
    const float* ws0      = (const float*)d_in[1];
    const float* wn0      = (const float*)d_in[2];
    const float* ws1      = (const float*)d_in[3];
    const float* wn1      = (const float*)d_in[4];
    const float* wout     = (const float*)d_in[5];
    const float* bout     = (const float*)d_in[6];
    const int*   node_ids = (const int*)d_in[7];
    const int*   adj      = (const int*)d_in[8];
    float* out = (float*)d_out;
    (void)in_sizes; (void)n_in; (void)out_size;

    // Host-side JAX key derivation (threefry, partitionable semantics):
    // key(42) = (0,42); folded_k = block(key,(0,k)); lower split key = block(folded,(0,1))
    uint32_t f0a, f0b, f1a, f1b, l0a, l0b, l1a, l1b;
    tf2x32(0u, 42u, 0u, 0u, f0a, f0b);
    tf2x32(0u, 42u, 0u, 1u, f1a, f1b);
    tf2x32(f0a, f0b, 0u, 1u, l0a, l0b);
    tf2x32(f1a, f1b, 0u, 1u, l1a, l1b);

    float *H1, *Mm1, *C1, *H0, *Mm0, *C0, *M2p, *Hf;
    cudaGetSymbolAddress((void**)&H1,  g_H1);
    cudaGetSymbolAddress((void**)&Mm1, g_M1);
    cudaGetSymbolAddress((void**)&C1,  g_C1);
    cudaGetSymbolAddress((void**)&H0,  g_H0);
    cudaGetSymbolAddress((void**)&Mm0, g_M0);
    cudaGetSymbolAddress((void**)&C0,  g_C0);
    cudaGetSymbolAddress((void**)&M2p, g_M2);
    cudaGetSymbolAddress((void**)&Hf,  g_Hf);

    k_hop1<<<M1SZ, FEAT>>>(feat, adj, node_ids, l0a, l0b, l1a, l1b);
    k_hop0<<<BATCH, FEAT>>>(feat, node_ids);
    k_gemm_relu<8><<<dim3(M1SZ / 64, 2), 128>>>(H1, Mm1, ws0, wn0, C1);
    k_gemm_relu<2><<<dim3(BATCH / 16, 2), 128>>>(H0, Mm0, ws0, wn0, C0);
    k_mean10<<<BATCH, FEAT>>>(C1, M2p);
    k_gemm_relu<2><<<dim3(BATCH / 16, 2), 128>>>(C0, M2p, ws1, wn1, Hf);
    k_final<<<BATCH, FEAT>>>(wout, bout, out);
}

// round 2
// speedup vs baseline: 1.1736x; 1.1736x over previous
#include <cuda_runtime.h>
#include <stdint.h>
#include <math.h>

#define FEAT     256
#define MAX_DEG  128
#define BATCH    1024
#define NS0      10
#define NS1      25
#define M1SZ     (BATCH * NS0)   /* 10240 */
#define RROWS    4               /* batch rows per tail block */

// ---------------- scratch ----------------
__device__ float g_H1[M1SZ * FEAT];   // features[s1]            [10240,256]
__device__ float g_M1[M1SZ * FEAT];   // mean of 25 hop-2 rows   [10240,256]
__device__ float g_C1[M1SZ * FEAT];   // layer0 hop1 output      [10240,256]

// ---------------- threefry2x32 (JAX-compatible, 20 rounds) ----------------
__host__ __device__ __forceinline__ uint32_t rotl32_(uint32_t x, int r) {
    return (x << r) | (x >> (32 - r));
}

__host__ __device__ inline void tf2x32(uint32_t k0, uint32_t k1,
                                       uint32_t x0, uint32_t x1,
                                       uint32_t &o0, uint32_t &o1) {
    uint32_t ks2 = k0 ^ k1 ^ 0x1BD11BDAu;
    x0 += k0; x1 += k1;
#define TFR(r) { x0 += x1; x1 = rotl32_(x1, (r)); x1 ^= x0; }
    TFR(13) TFR(15) TFR(26) TFR(6)
    x0 += k1;  x1 += ks2 + 1u;
    TFR(17) TFR(29) TFR(16) TFR(24)
    x0 += ks2; x1 += k0 + 2u;
    TFR(13) TFR(15) TFR(26) TFR(6)
    x0 += k0;  x1 += k1 + 3u;
    TFR(17) TFR(29) TFR(16) TFR(24)
    x0 += k1;  x1 += ks2 + 4u;
    TFR(13) TFR(15) TFR(26) TFR(6)
    x0 += ks2; x1 += k0 + 5u;
#undef TFR
    o0 = x0; o1 = x1;
}

__device__ __forceinline__ int rnd_col(uint32_t k0, uint32_t k1, uint32_t t) {
    uint32_t a, b;
    tf2x32(k0, k1, 0u, t, a, b);
    return (int)((a ^ b) & (uint32_t)(MAX_DEG - 1));
}

// ---------------- fused sample + gather + mean for hop 1 ----------------
__global__ void __launch_bounds__(FEAT)
k_hop1(const float* __restrict__ feat, const int* __restrict__ adj,
       const int* __restrict__ node_ids,
       uint32_t l0a, uint32_t l0b, uint32_t l1a, uint32_t l1b) {
    const int j = blockIdx.x;
    const int tid = threadIdx.x;
    __shared__ int s2s[NS1];
    __shared__ int s1sh;
    if (tid == 0) {
        int c0 = rnd_col(l0a, l0b, (uint32_t)j);
        s1sh = adj[(size_t)node_ids[j / NS0] * MAX_DEG + c0];
    }
    __syncthreads();
    const int s1v = s1sh;
    if (tid < NS1) {
        int c1 = rnd_col(l1a, l1b, (uint32_t)(j * NS1 + tid));
        s2s[tid] = adj[(size_t)s1v * MAX_DEG + c1];
    }
    __syncthreads();
    g_H1[(size_t)j * FEAT + tid] = feat[(size_t)s1v * FEAT + tid];
    float acc = 0.f;
#pragma unroll
    for (int s = 0; s < NS1; s++)
        acc += feat[(size_t)s2s[s] * FEAT + tid];
    g_M1[(size_t)j * FEAT + tid] = acc * (1.0f / NS1);
}

// ---------------- big GEMM: C1 = relu([H1@ws0 | M1@wn0]) ----------------
template<int TM>
__global__ void __launch_bounds__(128)
k_gemm_relu(const float* __restrict__ A0, const float* __restrict__ A1,
            const float* __restrict__ W0, const float* __restrict__ W1,
            float* __restrict__ C) {
    constexpr int BM = TM * 8;
    const float* __restrict__ A = blockIdx.y ? A1 : A0;
    const float* __restrict__ W = blockIdx.y ? W1 : W0;
    const int colOff = blockIdx.y * 128;
    const int m0 = blockIdx.x * BM;
    __shared__ float As[16][BM];
    __shared__ float Bs[16][128];
    const int tid = threadIdx.x;
    const int tn = tid & 15;
    const int tm = tid >> 4;
    float acc[TM][8];
#pragma unroll
    for (int x = 0; x < TM; x++)
#pragma unroll
        for (int y = 0; y < 8; y++) acc[x][y] = 0.f;

    for (int k0 = 0; k0 < FEAT; k0 += 16) {
        constexpr int NF4A = BM * 4;
#pragma unroll
        for (int i = 0; i < (NF4A + 127) / 128; i++) {
            int idx = i * 128 + tid;
            if ((NF4A % 128 == 0) || (idx < NF4A)) {
                int r = idx >> 2, q = idx & 3;
                float4 v = *reinterpret_cast<const float4*>(
                    A + (size_t)(m0 + r) * FEAT + k0 + q * 4);
                As[q * 4 + 0][r] = v.x; As[q * 4 + 1][r] = v.y;
                As[q * 4 + 2][r] = v.z; As[q * 4 + 3][r] = v.w;
            }
        }
#pragma unroll
        for (int i = 0; i < 4; i++) {
            int idx = i * 128 + tid;
            int r = idx >> 5, c = (idx & 31) * 4;
            *reinterpret_cast<float4*>(&Bs[r][c]) =
                *reinterpret_cast<const float4*>(W + (size_t)(k0 + r) * 128 + c);
        }
        __syncthreads();
#pragma unroll
        for (int kk = 0; kk < 16; kk++) {
            float a[TM], b[8];
#pragma unroll
            for (int x = 0; x < TM; x++) a[x] = As[kk][tm * TM + x];
#pragma unroll
            for (int y = 0; y < 8; y++) b[y] = Bs[kk][tn * 8 + y];
#pragma unroll
            for (int x = 0; x < TM; x++)
#pragma unroll
                for (int y = 0; y < 8; y++)
                    acc[x][y] = fmaf(a[x], b[y], acc[x][y]);
        }
        __syncthreads();
    }
#pragma unroll
    for (int x = 0; x < TM; x++) {
        const int m = m0 + tm * TM + x;
        float4 v0 = make_float4(fmaxf(acc[x][0], 0.f), fmaxf(acc[x][1], 0.f),
                                fmaxf(acc[x][2], 0.f), fmaxf(acc[x][3], 0.f));
        float4 v1 = make_float4(fmaxf(acc[x][4], 0.f), fmaxf(acc[x][5], 0.f),
                                fmaxf(acc[x][6], 0.f), fmaxf(acc[x][7], 0.f));
        float* p = C + (size_t)m * FEAT + colOff + tn * 8;
        *reinterpret_cast<float4*>(p) = v0;
        *reinterpret_cast<float4*>(p + 4) = v1;
    }
}

// ---------------- fused tail: hop0 gather/means + both small GEMMs +
//                  l2-normalize + final dot, RROWS batch rows per block ----
__global__ void __launch_bounds__(256)
k_tail(const float* __restrict__ feat, const int* __restrict__ node_ids,
       const float* __restrict__ ws0, const float* __restrict__ wn0,
       const float* __restrict__ ws1, const float* __restrict__ wn1,
       const float* __restrict__ w_out, const float* __restrict__ b_out,
       float* __restrict__ out) {
    // As[0][k][r] = self operand, As[1][k][r] = neigh operand (k = 0..255)
    __shared__ float As[2][FEAT][RROWS];           // 8 KB
    __shared__ float red[8][2 * RROWS];
    __shared__ float fin[2 * RROWS];

    const int t   = threadIdx.x;
    const int h   = t >> 7;        // 0 = self half, 1 = neigh half
    const int col = t & 127;
    const int i0  = blockIdx.x * RROWS;

    // ---- stage layer-0 inputs (feature index = t) ----
#pragma unroll
    for (int r = 0; r < RROWS; r++) {
        const int nid = node_ids[i0 + r];
        As[0][t][r] = feat[(size_t)nid * FEAT + t];
        float acc = 0.f;
#pragma unroll
        for (int s = 0; s < NS0; s++)
            acc += g_H1[(size_t)((i0 + r) * NS0 + s) * FEAT + t];
        As[1][t][r] = acc * (1.0f / NS0);
    }
    __syncthreads();

    // ---- layer-0 GEMM: thread owns output column t (= h*128+col) ----
    const float* __restrict__ W0 = h ? wn0 : ws0;
    float accA[RROWS] = {0.f, 0.f, 0.f, 0.f};
#pragma unroll 16
    for (int k = 0; k < FEAT; k++) {
        const float w = W0[k * 128 + col];
        const float4 a = *reinterpret_cast<const float4*>(&As[h][k][0]);
        accA[0] = fmaf(a.x, w, accA[0]);
        accA[1] = fmaf(a.y, w, accA[1]);
        accA[2] = fmaf(a.z, w, accA[2]);
        accA[3] = fmaf(a.w, w, accA[3]);
    }
    __syncthreads();

    // ---- write C0 row (this thread's concat index is exactly t) as layer-1
    //      self operand, and stage M2 = mean10(C1) as neigh operand ----
#pragma unroll
    for (int r = 0; r < RROWS; r++)
        As[0][t][r] = fmaxf(accA[r], 0.f);
#pragma unroll
    for (int r = 0; r < RROWS; r++) {
        float acc = 0.f;
#pragma unroll
        for (int s = 0; s < NS0; s++)
            acc += g_C1[(size_t)((i0 + r) * NS0 + s) * FEAT + t];
        As[1][t][r] = acc * (1.0f / NS0);
    }
    __syncthreads();

    // ---- layer-1 GEMM ----
    const float* __restrict__ W1 = h ? wn1 : ws1;
    float accB[RROWS] = {0.f, 0.f, 0.f, 0.f};
#pragma unroll 16
    for (int k = 0; k < FEAT; k++) {
        const float w = W1[k * 128 + col];
        const float4 a = *reinterpret_cast<const float4*>(&As[h][k][0]);
        accB[0] = fmaf(a.x, w, accB[0]);
        accB[1] = fmaf(a.y, w, accB[1]);
        accB[2] = fmaf(a.z, w, accB[2]);
        accB[3] = fmaf(a.w, w, accB[3]);
    }

    // ---- epilogue: relu, row l2-norm, dot with w_out ----
    const float wo = w_out[t];
    float ss[RROWS], dv[RROWS];
#pragma unroll
    for (int r = 0; r < RROWS; r++) {
        const float hv = fmaxf(accB[r], 0.f);
        ss[r] = hv * hv;
        dv[r] = hv * wo;
    }
#pragma unroll
    for (int off = 16; off > 0; off >>= 1) {
#pragma unroll
        for (int r = 0; r < RROWS; r++) {
            ss[r] += __shfl_down_sync(0xffffffffu, ss[r], off);
            dv[r] += __shfl_down_sync(0xffffffffu, dv[r], off);
        }
    }
    const int lane = t & 31, wid = t >> 5;
    if (lane == 0) {
#pragma unroll
        for (int r = 0; r < RROWS; r++) {
            red[wid][r]         = ss[r];
            red[wid][RROWS + r] = dv[r];
        }
    }
    __syncthreads();
    if (t < 2 * RROWS) {
        float v = 0.f;
#pragma unroll
        for (int w = 0; w < 8; w++) v += red[w][t];
        fin[t] = v;
    }
    __syncthreads();
    if (t < RROWS)
        out[i0 + t] = fin[RROWS + t] / sqrtf(fmaxf(fin[t], 1e-12f)) + b_out[0];
}

// ---------------- launch ----------------
extern "C" void kernel_launch(void* const* d_in, const int* in_sizes, int n_in,
                              void* d_out, int out_size) {
    const float* feat     = (const float*)d_in[0];
    const float* ws0      = (const float*)d_in[1];
    const float* wn0      = (const float*)d_in[2];
    const float* ws1      = (const float*)d_in[3];
    const float* wn1      = (const float*)d_in[4];
    const float* wout     = (const float*)d_in[5];
    const float* bout     = (const float*)d_in[6];
    const int*   node_ids = (const int*)d_in[7];
    const int*   adj      = (const int*)d_in[8];
    float* out = (float*)d_out;
    (void)in_sizes; (void)n_in; (void)out_size;

    // Host-side JAX key derivation (threefry, partitionable semantics)
    uint32_t f0a, f0b, f1a, f1b, l0a, l0b, l1a, l1b;
    tf2x32(0u, 42u, 0u, 0u, f0a, f0b);
    tf2x32(0u, 42u, 0u, 1u, f1a, f1b);
    tf2x32(f0a, f0b, 0u, 1u, l0a, l0b);
    tf2x32(f1a, f1b, 0u, 1u, l1a, l1b);

    float *H1, *Mm1, *C1;
    cudaGetSymbolAddress((void**)&H1,  g_H1);
    cudaGetSymbolAddress((void**)&Mm1, g_M1);
    cudaGetSymbolAddress((void**)&C1,  g_C1);

    k_hop1<<<M1SZ, FEAT>>>(feat, adj, node_ids, l0a, l0b, l1a, l1b);
    k_gemm_relu<8><<<dim3(M1SZ / 64, 2), 128>>>(H1, Mm1, ws0, wn0, C1);
    k_tail<<<BATCH / RROWS, 256>>>(feat, node_ids, ws0, wn0, ws1, wn1,
                                   wout, bout, out);
}

// round 4
// speedup vs baseline: 1.4431x; 1.2296x over previous
#include <cuda_runtime.h>
#include <stdint.h>
#include <math.h>

#define FEAT     256
#define MAX_DEG  128
#define BATCH    1024
#define NS0      10
#define NS1      25
#define M1SZ     (BATCH * NS0)   /* 10240 */
#define RROWS    8               /* batch rows per tail block */

// ---------------- scratch ----------------
__device__ float g_H1[M1SZ * FEAT];      // features[s1]            [10240,256]
__device__ float g_M1[M1SZ * FEAT];      // mean of 25 hop-2 rows   [10240,256]
__device__ float g_C1[M1SZ * FEAT];      // layer0 hop1 output      [10240,256]
__device__ float g_WT[2 * 128 * FEAT];   // ws0,wn0 K-major, tf32-rounded

// ---------------- threefry2x32 (JAX-compatible, 20 rounds) ----------------
__host__ __device__ __forceinline__ uint32_t rotl32_(uint32_t x, int r) {
    return (x << r) | (x >> (32 - r));
}
__host__ __device__ inline void tf2x32(uint32_t k0, uint32_t k1,
                                       uint32_t x0, uint32_t x1,
                                       uint32_t &o0, uint32_t &o1) {
    uint32_t ks2 = k0 ^ k1 ^ 0x1BD11BDAu;
    x0 += k0; x1 += k1;
#define TFR(r) { x0 += x1; x1 = rotl32_(x1, (r)); x1 ^= x0; }
    TFR(13) TFR(15) TFR(26) TFR(6)
    x0 += k1;  x1 += ks2 + 1u;
    TFR(17) TFR(29) TFR(16) TFR(24)
    x0 += ks2; x1 += k0 + 2u;
    TFR(13) TFR(15) TFR(26) TFR(6)
    x0 += k0;  x1 += k1 + 3u;
    TFR(17) TFR(29) TFR(16) TFR(24)
    x0 += k1;  x1 += ks2 + 4u;
    TFR(13) TFR(15) TFR(26) TFR(6)
    x0 += ks2; x1 += k0 + 5u;
#undef TFR
    o0 = x0; o1 = x1;
}
__device__ __forceinline__ int rnd_col(uint32_t k0, uint32_t k1, uint32_t t) {
    uint32_t a, b;
    tf2x32(k0, k1, 0u, t, a, b);
    return (int)((a ^ b) & (uint32_t)(MAX_DEG - 1));
}

// ---------------- mma.sync tf32 helpers ----------------
__device__ __forceinline__ void mma_tf32(float c[4], const uint32_t a[4],
                                         const uint32_t b[2]) {
    asm volatile(
        "mma.sync.aligned.m16n8k8.row.col.f32.tf32.tf32.f32 "
        "{%0,%1,%2,%3}, {%4,%5,%6,%7}, {%8,%9}, {%0,%1,%2,%3};"
        : "+f"(c[0]), "+f"(c[1]), "+f"(c[2]), "+f"(c[3])
        : "r"(a[0]), "r"(a[1]), "r"(a[2]), "r"(a[3]), "r"(b[0]), "r"(b[1]));
}
__device__ __forceinline__ float4 cvt4_tf32(float4 v) {
    asm("cvt.rna.tf32.f32 %0, %0;" : "+f"(v.x));
    asm("cvt.rna.tf32.f32 %0, %0;" : "+f"(v.y));
    asm("cvt.rna.tf32.f32 %0, %0;" : "+f"(v.z));
    asm("cvt.rna.tf32.f32 %0, %0;" : "+f"(v.w));
    return v;
}

// ---------------- weight transpose + tf32 rounding ----------------
// WT[mat][n*256+k] = tf32(w[mat][k*128+n])   (K-major == col-major B for mma)
__global__ void __launch_bounds__(256)
k_wT(const float* __restrict__ w0, const float* __restrict__ w1) {
    __shared__ float tile[32][33];
    const float* W = blockIdx.y ? w1 : w0;
    float* WT = g_WT + blockIdx.y * (128 * FEAT);
    const int k0 = (blockIdx.x >> 2) * 32;
    const int n0 = (blockIdx.x & 3) * 32;
    const int c = threadIdx.x & 31, rw = threadIdx.x >> 5;
#pragma unroll
    for (int r = rw; r < 32; r += 8) {
        float v = W[(k0 + r) * 128 + n0 + c];
        asm("cvt.rna.tf32.f32 %0, %0;" : "+f"(v));
        tile[r][c] = v;
    }
    __syncthreads();
#pragma unroll
    for (int r = rw; r < 32; r += 8)
        WT[(n0 + r) * FEAT + k0 + c] = tile[c][r];
}

// ---------------- fused sample + gather + mean for hop 1 (float4) --------
__global__ void __launch_bounds__(256)
k_hop1(const float4* __restrict__ feat4, const int* __restrict__ adj,
       const int* __restrict__ node_ids,
       uint32_t l0a, uint32_t l0b, uint32_t l1a, uint32_t l1b) {
    const int tid = threadIdx.x;
    const int j0 = blockIdx.x * 4;
    __shared__ int s1sh[4];
    __shared__ int s2s[4][NS1];
    if (tid < 4) {
        int j = j0 + tid;
        int c0 = rnd_col(l0a, l0b, (uint32_t)j);
        s1sh[tid] = adj[node_ids[j / NS0] * MAX_DEG + c0];
    }
    __syncthreads();
    if (tid < 4 * NS1) {
        int lj = tid / NS1, s = tid - lj * NS1;
        int c1 = rnd_col(l1a, l1b, (uint32_t)((j0 + lj) * NS1 + s));
        s2s[lj][s] = adj[s1sh[lj] * MAX_DEG + c1];
    }
    __syncthreads();
    const int lj = tid >> 6, c = tid & 63;
    const int j = j0 + lj;
    float4* H14 = (float4*)g_H1;
    float4* M14 = (float4*)g_M1;
    H14[j * 64 + c] = feat4[s1sh[lj] * 64 + c];
    float ax = 0.f, ay = 0.f, az = 0.f, aw = 0.f;
#pragma unroll
    for (int s = 0; s < NS1; s++) {
        float4 v = feat4[s2s[lj][s] * 64 + c];
        ax += v.x; ay += v.y; az += v.z; aw += v.w;
    }
    const float inv = 1.0f / NS1;
    M14[j * 64 + c] = make_float4(ax * inv, ay * inv, az * inv, aw * inv);
}

// ---------------- tf32 mma.sync GEMM: C1 = relu([H1@ws0 | M1@wn0]) --------
// grid (80, 2): 128 M-rows per block, half = which [A,W] pair / 128-col half.
// 8 warps in 2x4 grid, each warp 64x32 via m16n8k8, K-chunks of 32.
__global__ void __launch_bounds__(256)
k_gemm_mma(const float* __restrict__ A0, const float* __restrict__ A1,
           float* __restrict__ C) {
    __shared__ float As[128][36];
    __shared__ float Bs[128][36];
    const int tid = threadIdx.x, lane = tid & 31, wid = tid >> 5;
    const int wr = wid & 1, wc = wid >> 1;
    const int m0 = blockIdx.x * 128;
    const float4* __restrict__ A4 =
        (const float4*)(blockIdx.y ? A1 : A0);
    const float4* __restrict__ B4 =
        (const float4*)(g_WT + blockIdx.y * (128 * FEAT));
    const int colOff = blockIdx.y * 128;

    float acc[4][4][4];
#pragma unroll
    for (int mt = 0; mt < 4; mt++)
#pragma unroll
        for (int nt = 0; nt < 4; nt++)
#pragma unroll
            for (int q = 0; q < 4; q++) acc[mt][nt][q] = 0.f;

    const int grow = tid >> 3, gq = tid & 7;   // gmem-stage row/quad

    for (int cc = 0; cc < 8; cc++) {
#pragma unroll
        for (int u = 0; u < 4; u++) {
            const int row = grow + u * 32;
            float4 va = cvt4_tf32(A4[(size_t)(m0 + row) * 64 + cc * 8 + gq]);
            float4 vb = B4[(size_t)row * 64 + cc * 8 + gq];  // pre-rounded
            As[row][gq * 4 + 0] = va.x; As[row][gq * 4 + 1] = va.y;
            As[row][gq * 4 + 2] = va.z; As[row][gq * 4 + 3] = va.w;
            Bs[row][gq * 4 + 0] = vb.x; Bs[row][gq * 4 + 1] = vb.y;
            Bs[row][gq * 4 + 2] = vb.z; Bs[row][gq * 4 + 3] = vb.w;
        }
        __syncthreads();
#pragma unroll
        for (int ks = 0; ks < 4; ks++) {
            const int k8 = ks * 8;
            uint32_t af[4][4], bf[4][2];
#pragma unroll
            for (int mt = 0; mt < 4; mt++) {
                const int rb = wr * 64 + mt * 16;
                af[mt][0] = __float_as_uint(As[rb + (lane >> 2)][k8 + (lane & 3)]);
                af[mt][1] = __float_as_uint(As[rb + 8 + (lane >> 2)][k8 + (lane & 3)]);
                af[mt][2] = __float_as_uint(As[rb + (lane >> 2)][k8 + 4 + (lane & 3)]);
                af[mt][3] = __float_as_uint(As[rb + 8 + (lane >> 2)][k8 + 4 + (lane & 3)]);
            }
#pragma unroll
            for (int nt = 0; nt < 4; nt++) {
                const int nb = wc * 32 + nt * 8;
                bf[nt][0] = __float_as_uint(Bs[nb + (lane >> 2)][k8 + (lane & 3)]);
                bf[nt][1] = __float_as_uint(Bs[nb + (lane >> 2)][k8 + 4 + (lane & 3)]);
            }
#pragma unroll
            for (int mt = 0; mt < 4; mt++)
#pragma unroll
                for (int nt = 0; nt < 4; nt++)
                    mma_tf32(acc[mt][nt], af[mt], bf[nt]);
        }
        __syncthreads();
    }

    // epilogue: relu + store (c0,c1 = row, cols 2t..2t+1; c2,c3 = row+8)
#pragma unroll
    for (int mt = 0; mt < 4; mt++) {
        const int row0 = m0 + wr * 64 + mt * 16 + (lane >> 2);
#pragma unroll
        for (int nt = 0; nt < 4; nt++) {
            const int col0 = colOff + wc * 32 + nt * 8 + (lane & 3) * 2;
            float2 v0 = make_float2(fmaxf(acc[mt][nt][0], 0.f),
                                    fmaxf(acc[mt][nt][1], 0.f));
            float2 v1 = make_float2(fmaxf(acc[mt][nt][2], 0.f),
                                    fmaxf(acc[mt][nt][3], 0.f));
            *(float2*)&C[(size_t)row0 * FEAT + col0] = v0;
            *(float2*)&C[(size_t)(row0 + 8) * FEAT + col0] = v1;
        }
    }
}

// ---------------- fused tail (RROWS=8) ----------------
__global__ void __launch_bounds__(256)
k_tail(const float* __restrict__ feat, const int* __restrict__ node_ids,
       const float* __restrict__ ws0, const float* __restrict__ wn0,
       const float* __restrict__ ws1, const float* __restrict__ wn1,
       const float* __restrict__ w_out, const float* __restrict__ b_out,
       float* __restrict__ out) {
    __shared__ float As[2][RROWS][FEAT];   // 16 KB
    __shared__ float red[8][2 * RROWS];
    __shared__ float fin[2 * RROWS];

    const int t   = threadIdx.x;
    const int h   = t >> 7;
    const int col = t & 127;
    const int i0  = blockIdx.x * RROWS;

#pragma unroll
    for (int r = 0; r < RROWS; r++) {
        const int nid = node_ids[i0 + r];
        As[0][r][t] = feat[(size_t)nid * FEAT + t];
        float acc = 0.f;
#pragma unroll
        for (int s = 0; s < NS0; s++)
            acc += g_H1[(size_t)((i0 + r) * NS0 + s) * FEAT + t];
        As[1][r][t] = acc * (1.0f / NS0);
    }
    __syncthreads();

    const float* __restrict__ W0 = h ? wn0 : ws0;
    float accA[RROWS];
#pragma unroll
    for (int r = 0; r < RROWS; r++) accA[r] = 0.f;
#pragma unroll 4
    for (int k = 0; k < FEAT; k += 4) {
        float w0 = W0[(k + 0) * 128 + col];
        float w1 = W0[(k + 1) * 128 + col];
        float w2 = W0[(k + 2) * 128 + col];
        float w3 = W0[(k + 3) * 128 + col];
#pragma unroll
        for (int r = 0; r < RROWS; r++) {
            const float4 a = *reinterpret_cast<const float4*>(&As[h][r][k]);
            accA[r] = fmaf(a.x, w0, accA[r]);
            accA[r] = fmaf(a.y, w1, accA[r]);
            accA[r] = fmaf(a.z, w2, accA[r]);
            accA[r] = fmaf(a.w, w3, accA[r]);
        }
    }
    __syncthreads();

#pragma unroll
    for (int r = 0; r < RROWS; r++)
        As[0][r][t] = fmaxf(accA[r], 0.f);
#pragma unroll
    for (int r = 0; r < RROWS; r++) {
        float acc = 0.f;
#pragma unroll
        for (int s = 0; s < NS0; s++)
            acc += g_C1[(size_t)((i0 + r) * NS0 + s) * FEAT + t];
        As[1][r][t] = acc * (1.0f / NS0);
    }
    __syncthreads();

    const float* __restrict__ W1 = h ? wn1 : ws1;
    float accB[RROWS];
#pragma unroll
    for (int r = 0; r < RROWS; r++) accB[r] = 0.f;
#pragma unroll 4
    for (int k = 0; k < FEAT; k += 4) {
        float w0 = W1[(k + 0) * 128 + col];
        float w1 = W1[(k + 1) * 128 + col];
        float w2 = W1[(k + 2) * 128 + col];
        float w3 = W1[(k + 3) * 128 + col];
#pragma unroll
        for (int r = 0; r < RROWS; r++) {
            const float4 a = *reinterpret_cast<const float4*>(&As[h][r][k]);
            accB[r] = fmaf(a.x, w0, accB[r]);
            accB[r] = fmaf(a.y, w1, accB[r]);
            accB[r] = fmaf(a.z, w2, accB[r]);
            accB[r] = fmaf(a.w, w3, accB[r]);
        }
    }

    const float wo = w_out[t];
    float ss[RROWS], dv[RROWS];
#pragma unroll
    for (int r = 0; r < RROWS; r++) {
        const float hv = fmaxf(accB[r], 0.f);
        ss[r] = hv * hv;
        dv[r] = hv * wo;
    }
#pragma unroll
    for (int off = 16; off > 0; off >>= 1) {
#pragma unroll
        for (int r = 0; r < RROWS; r++) {
            ss[r] += __shfl_down_sync(0xffffffffu, ss[r], off);
            dv[r] += __shfl_down_sync(0xffffffffu, dv[r], off);
        }
    }
    const int lane = t & 31, wid = t >> 5;
    if (lane == 0) {
#pragma unroll
        for (int r = 0; r < RROWS; r++) {
            red[wid][r]         = ss[r];
            red[wid][RROWS + r] = dv[r];
        }
    }
    __syncthreads();
    if (t < 2 * RROWS) {
        float v = 0.f;
#pragma unroll
        for (int w = 0; w < 8; w++) v += red[w][t];
        fin[t] = v;
    }
    __syncthreads();
    if (t < RROWS)
        out[i0 + t] = fin[RROWS + t] / sqrtf(fmaxf(fin[t], 1e-12f)) + b_out[0];
}

// ---------------- launch ----------------
extern "C" void kernel_launch(void* const* d_in, const int* in_sizes, int n_in,
                              void* d_out, int out_size) {
    const float* feat     = (const float*)d_in[0];
    const float* ws0      = (const float*)d_in[1];
    const float* wn0      = (const float*)d_in[2];
    const float* ws1      = (const float*)d_in[3];
    const float* wn1      = (const float*)d_in[4];
    const float* wout     = (const float*)d_in[5];
    const float* bout     = (const float*)d_in[6];
    const int*   node_ids = (const int*)d_in[7];
    const int*   adj      = (const int*)d_in[8];
    float* out = (float*)d_out;
    (void)in_sizes; (void)n_in; (void)out_size;

    uint32_t f0a, f0b, f1a, f1b, l0a, l0b, l1a, l1b;
    tf2x32(0u, 42u, 0u, 0u, f0a, f0b);
    tf2x32(0u, 42u, 0u, 1u, f1a, f1b);
    tf2x32(f0a, f0b, 0u, 1u, l0a, l0b);
    tf2x32(f1a, f1b, 0u, 1u, l1a, l1b);

    float *H1, *Mm1, *C1;
    cudaGetSymbolAddress((void**)&H1,  g_H1);
    cudaGetSymbolAddress((void**)&Mm1, g_M1);
    cudaGetSymbolAddress((void**)&C1,  g_C1);

    k_wT<<<dim3(32, 2), 256>>>(ws0, wn0);
    k_hop1<<<M1SZ / 4, 256>>>((const float4*)feat, adj, node_ids,
                              l0a, l0b, l1a, l1b);
    k_gemm_mma<<<dim3(M1SZ / 128, 2), 256>>>(H1, Mm1, C1);
    k_tail<<<BATCH / RROWS, 256>>>(feat, node_ids, ws0, wn0, ws1, wn1,
                                   wout, bout, out);
}

// round 5
// speedup vs baseline: 1.7737x; 1.2291x over previous
#include <cuda_runtime.h>
#include <stdint.h>
#include <math.h>

#define FEAT     256
#define MAX_DEG  128
#define BATCH    1024
#define NS0      10
#define NS1      25
#define M1SZ     (BATCH * NS0)     /* 10240 */
#define MEXT     (M1SZ + BATCH)    /* 11264: hop1 rows + batch rows */
#define RROWS    4                 /* batch rows per tail block */
#define BM       64                /* GEMM M-tile */

// ---------------- scratch ----------------
__device__ float g_H1[MEXT * FEAT];      // self operands (hop1 rows + H0 rows)
__device__ float g_M1[MEXT * FEAT];      // neigh means  (mean25 + M0 rows)
__device__ float g_C1[MEXT * FEAT];      // layer0 outputs (C1 rows + C0 rows)
__device__ float g_WT[2 * 128 * FEAT];   // ws0,wn0 K-major, tf32-rounded

// ---------------- threefry2x32 (JAX-compatible, 20 rounds) ----------------
__host__ __device__ __forceinline__ uint32_t rotl32_(uint32_t x, int r) {
    return (x << r) | (x >> (32 - r));
}
__host__ __device__ inline void tf2x32(uint32_t k0, uint32_t k1,
                                       uint32_t x0, uint32_t x1,
                                       uint32_t &o0, uint32_t &o1) {
    uint32_t ks2 = k0 ^ k1 ^ 0x1BD11BDAu;
    x0 += k0; x1 += k1;
#define TFR(r) { x0 += x1; x1 = rotl32_(x1, (r)); x1 ^= x0; }
    TFR(13) TFR(15) TFR(26) TFR(6)
    x0 += k1;  x1 += ks2 + 1u;
    TFR(17) TFR(29) TFR(16) TFR(24)
    x0 += ks2; x1 += k0 + 2u;
    TFR(13) TFR(15) TFR(26) TFR(6)
    x0 += k0;  x1 += k1 + 3u;
    TFR(17) TFR(29) TFR(16) TFR(24)
    x0 += k1;  x1 += ks2 + 4u;
    TFR(13) TFR(15) TFR(26) TFR(6)
    x0 += ks2; x1 += k0 + 5u;
#undef TFR
    o0 = x0; o1 = x1;
}
__device__ __forceinline__ int rnd_col(uint32_t k0, uint32_t k1, uint32_t t) {
    uint32_t a, b;
    tf2x32(k0, k1, 0u, t, a, b);
    return (int)((a ^ b) & (uint32_t)(MAX_DEG - 1));
}

// ---------------- helpers ----------------
__device__ __forceinline__ void mma_tf32(float c[4], const uint32_t a[4],
                                         const uint32_t b[2]) {
    asm volatile(
        "mma.sync.aligned.m16n8k8.row.col.f32.tf32.tf32.f32 "
        "{%0,%1,%2,%3}, {%4,%5,%6,%7}, {%8,%9}, {%0,%1,%2,%3};"
        : "+f"(c[0]), "+f"(c[1]), "+f"(c[2]), "+f"(c[3])
        : "r"(a[0]), "r"(a[1]), "r"(a[2]), "r"(a[3]), "r"(b[0]), "r"(b[1]));
}
__device__ __forceinline__ uint32_t smem_u32(const void* p) {
    return (uint32_t)__cvta_generic_to_shared(p);
}
__device__ __forceinline__ void cp16(uint32_t s, const void* g) {
    asm volatile("cp.async.cg.shared.global [%0], [%1], 16;" :: "r"(s), "l"(g));
}
#define CP_COMMIT() asm volatile("cp.async.commit_group;" ::: "memory")
#define CP_WAIT0()  asm volatile("cp.async.wait_group 0;" ::: "memory")

// ---------------- weight transpose + tf32 rounding (layer-0 weights) ------
__global__ void __launch_bounds__(256)
k_wT(const float* __restrict__ w0, const float* __restrict__ w1) {
    __shared__ float tile[32][33];
    const float* W = blockIdx.y ? w1 : w0;
    float* WT = g_WT + blockIdx.y * (128 * FEAT);
    const int k0 = (blockIdx.x >> 2) * 32;
    const int n0 = (blockIdx.x & 3) * 32;
    const int c = threadIdx.x & 31, rw = threadIdx.x >> 5;
#pragma unroll
    for (int r = rw; r < 32; r += 8) {
        float v = W[(k0 + r) * 128 + n0 + c];
        asm("cvt.rna.tf32.f32 %0, %0;" : "+f"(v));
        tile[r][c] = v;
    }
    __syncthreads();
#pragma unroll
    for (int r = rw; r < 32; r += 8)
        WT[(n0 + r) * FEAT + k0 + c] = tile[c][r];
}

// ---------------- fused sample + gather + mean for hop 1 (float4) --------
__global__ void __launch_bounds__(256)
k_hop1(const float4* __restrict__ feat4, const int* __restrict__ adj,
       const int* __restrict__ node_ids,
       uint32_t l0a, uint32_t l0b, uint32_t l1a, uint32_t l1b) {
    const int tid = threadIdx.x;
    const int j0 = blockIdx.x * 4;
    __shared__ int s1sh[4];
    __shared__ int s2s[4][NS1];
    if (tid < 4) {
        int j = j0 + tid;
        int c0 = rnd_col(l0a, l0b, (uint32_t)j);
        s1sh[tid] = adj[node_ids[j / NS0] * MAX_DEG + c0];
    }
    __syncthreads();
    if (tid < 4 * NS1) {
        int lj = tid / NS1, s = tid - lj * NS1;
        int c1 = rnd_col(l1a, l1b, (uint32_t)((j0 + lj) * NS1 + s));
        s2s[lj][s] = adj[s1sh[lj] * MAX_DEG + c1];
    }
    __syncthreads();
    const int lj = tid >> 6, c = tid & 63;
    const int j = j0 + lj;
    float4* H14 = (float4*)g_H1;
    float4* M14 = (float4*)g_M1;
    H14[j * 64 + c] = feat4[s1sh[lj] * 64 + c];
    float ax = 0.f, ay = 0.f, az = 0.f, aw = 0.f;
#pragma unroll
    for (int s = 0; s < NS1; s++) {
        float4 v = feat4[s2s[lj][s] * 64 + c];
        ax += v.x; ay += v.y; az += v.z; aw += v.w;
    }
    const float inv = 1.0f / NS1;
    M14[j * 64 + c] = make_float4(ax * inv, ay * inv, az * inv, aw * inv);
}

// ---------------- batch rows: H0 gather + M0 = mean10(H1) -----------------
__global__ void __launch_bounds__(256)
k_hop0mean(const float4* __restrict__ feat4, const int* __restrict__ node_ids) {
    const int tid = threadIdx.x;
    const int lj = tid >> 6, c = tid & 63;
    const int i = blockIdx.x * 4 + lj;
    float4* H14 = (float4*)g_H1;
    float4* M14 = (float4*)g_M1;
    H14[(size_t)(M1SZ + i) * 64 + c] = feat4[(size_t)node_ids[i] * 64 + c];
    float ax = 0.f, ay = 0.f, az = 0.f, aw = 0.f;
#pragma unroll
    for (int s = 0; s < NS0; s++) {
        float4 v = H14[(size_t)(i * NS0 + s) * 64 + c];
        ax += v.x; ay += v.y; az += v.z; aw += v.w;
    }
    const float inv = 1.0f / NS0;
    M14[(size_t)(M1SZ + i) * 64 + c] = make_float4(ax * inv, ay * inv,
                                                   az * inv, aw * inv);
}

// ---------------- tf32 mma.sync GEMM, cp.async double-buffered ------------
// C1ext[MEXT,256] = relu([H1ext@ws0 | M1ext@wn0]); grid (MEXT/BM, 2).
// dyn smem: per buf: A 64x36 floats (2304) + B 128x36 (4608) = 6912 floats.
#define SA(b, r, c) sm[(b) * 6912 + (r) * 36 + (c)]
#define SB(b, r, c) sm[(b) * 6912 + 2304 + (r) * 36 + (c)]
#define G_SMEM (2 * 6912 * 4)

__global__ void __launch_bounds__(256)
k_gemm_mma(const float* __restrict__ A0, const float* __restrict__ A1,
           float* __restrict__ C) {
    extern __shared__ float sm[];
    const int tid = threadIdx.x, lane = tid & 31, wid = tid >> 5;
    const int wr = wid & 1, wc = wid >> 1;
    const int m0 = blockIdx.x * BM;
    const float4* __restrict__ A4 = (const float4*)(blockIdx.y ? A1 : A0);
    const float4* __restrict__ B4 =
        (const float4*)(g_WT + blockIdx.y * (128 * FEAT));
    const int colOff = blockIdx.y * 128;

    float acc[2][4][4];
#pragma unroll
    for (int mt = 0; mt < 2; mt++)
#pragma unroll
        for (int nt = 0; nt < 4; nt++)
#pragma unroll
            for (int q = 0; q < 4; q++) acc[mt][nt][q] = 0.f;

    // stage chunk cc into buffer b (cp.async, 16B each)
    auto stage = [&](int cc, int b) {
#pragma unroll
        for (int u = 0; u < 2; u++) {            // A: 512 float4
            int fid = u * 256 + tid;
            int row = fid >> 3, q = fid & 7;
            cp16(smem_u32(&SA(b, row, q * 4)),
                 &A4[(size_t)(m0 + row) * 64 + cc * 8 + q]);
        }
#pragma unroll
        for (int u = 0; u < 4; u++) {            // B: 1024 float4
            int fid = u * 256 + tid;
            int row = fid >> 3, q = fid & 7;
            cp16(smem_u32(&SB(b, row, q * 4)),
                 &B4[(size_t)row * 64 + cc * 8 + q]);
        }
        CP_COMMIT();
    };

    stage(0, 0);
    for (int cc = 0; cc < 8; cc++) {
        const int b = cc & 1;
        CP_WAIT0();
        __syncthreads();
        if (cc < 7) stage(cc + 1, b ^ 1);
#pragma unroll
        for (int ks = 0; ks < 4; ks++) {
            const int k8 = ks * 8;
            uint32_t af[2][4], bf[4][2];
#pragma unroll
            for (int mt = 0; mt < 2; mt++) {
                const int rb = wr * 32 + mt * 16;
                af[mt][0] = __float_as_uint(SA(b, rb + (lane >> 2), k8 + (lane & 3)));
                af[mt][1] = __float_as_uint(SA(b, rb + 8 + (lane >> 2), k8 + (lane & 3)));
                af[mt][2] = __float_as_uint(SA(b, rb + (lane >> 2), k8 + 4 + (lane & 3)));
                af[mt][3] = __float_as_uint(SA(b, rb + 8 + (lane >> 2), k8 + 4 + (lane & 3)));
            }
#pragma unroll
            for (int nt = 0; nt < 4; nt++) {
                const int nb = wc * 32 + nt * 8;
                bf[nt][0] = __float_as_uint(SB(b, nb + (lane >> 2), k8 + (lane & 3)));
                bf[nt][1] = __float_as_uint(SB(b, nb + (lane >> 2), k8 + 4 + (lane & 3)));
            }
#pragma unroll
            for (int mt = 0; mt < 2; mt++)
#pragma unroll
                for (int nt = 0; nt < 4; nt++)
                    mma_tf32(acc[mt][nt], af[mt], bf[nt]);
        }
        __syncthreads();
    }

#pragma unroll
    for (int mt = 0; mt < 2; mt++) {
        const int row0 = m0 + wr * 32 + mt * 16 + (lane >> 2);
#pragma unroll
        for (int nt = 0; nt < 4; nt++) {
            const int col0 = colOff + wc * 32 + nt * 8 + (lane & 3) * 2;
            float2 v0 = make_float2(fmaxf(acc[mt][nt][0], 0.f),
                                    fmaxf(acc[mt][nt][1], 0.f));
            float2 v1 = make_float2(fmaxf(acc[mt][nt][2], 0.f),
                                    fmaxf(acc[mt][nt][3], 0.f));
            *(float2*)&C[(size_t)row0 * FEAT + col0] = v0;
            *(float2*)&C[(size_t)(row0 + 8) * FEAT + col0] = v1;
        }
    }
}

// ---------------- tail: layer-1 GEMM + l2-norm + dot (RROWS=4) ------------
__global__ void __launch_bounds__(256)
k_tail(const float* __restrict__ ws1, const float* __restrict__ wn1,
       const float* __restrict__ w_out, const float* __restrict__ b_out,
       float* __restrict__ out) {
    __shared__ __align__(16) float As[2][RROWS][FEAT];   // 8 KB
    __shared__ float red[8][2 * RROWS];
    __shared__ float fin[2 * RROWS];

    const int t   = threadIdx.x;
    const int h   = t >> 7;
    const int col = t & 127;
    const int i0  = blockIdx.x * RROWS;

    // stage: self = C0 row (ext region), neigh = mean10(C1)
#pragma unroll
    for (int r = 0; r < RROWS; r++) {
        As[0][r][t] = g_C1[(size_t)(M1SZ + i0 + r) * FEAT + t];
        float acc = 0.f;
#pragma unroll
        for (int s = 0; s < NS0; s++)
            acc += g_C1[(size_t)((i0 + r) * NS0 + s) * FEAT + t];
        As[1][r][t] = acc * (1.0f / NS0);
    }
    __syncthreads();

    const float* __restrict__ W1 = h ? wn1 : ws1;
    float accB[RROWS];
#pragma unroll
    for (int r = 0; r < RROWS; r++) accB[r] = 0.f;
#pragma unroll 4
    for (int k = 0; k < FEAT; k += 4) {
        float w0 = W1[(k + 0) * 128 + col];
        float w1 = W1[(k + 1) * 128 + col];
        float w2 = W1[(k + 2) * 128 + col];
        float w3 = W1[(k + 3) * 128 + col];
#pragma unroll
        for (int r = 0; r < RROWS; r++) {
            const float4 a = *reinterpret_cast<const float4*>(&As[h][r][k]);
            accB[r] = fmaf(a.x, w0, accB[r]);
            accB[r] = fmaf(a.y, w1, accB[r]);
            accB[r] = fmaf(a.z, w2, accB[r]);
            accB[r] = fmaf(a.w, w3, accB[r]);
        }
    }

    const float wo = w_out[t];
    float ss[RROWS], dv[RROWS];
#pragma unroll
    for (int r = 0; r < RROWS; r++) {
        const float hv = fmaxf(accB[r], 0.f);
        ss[r] = hv * hv;
        dv[r] = hv * wo;
    }
#pragma unroll
    for (int off = 16; off > 0; off >>= 1) {
#pragma unroll
        for (int r = 0; r < RROWS; r++) {
            ss[r] += __shfl_down_sync(0xffffffffu, ss[r], off);
            dv[r] += __shfl_down_sync(0xffffffffu, dv[r], off);
        }
    }
    const int lane = t & 31, wid = t >> 5;
    if (lane == 0) {
#pragma unroll
        for (int r = 0; r < RROWS; r++) {
            red[wid][r]         = ss[r];
            red[wid][RROWS + r] = dv[r];
        }
    }
    __syncthreads();
    if (t < 2 * RROWS) {
        float v = 0.f;
#pragma unroll
        for (int w = 0; w < 8; w++) v += red[w][t];
        fin[t] = v;
    }
    __syncthreads();
    if (t < RROWS)
        out[i0 + t] = fin[RROWS + t] / sqrtf(fmaxf(fin[t], 1e-12f)) + b_out[0];
}

// ---------------- launch ----------------
extern "C" void kernel_launch(void* const* d_in, const int* in_sizes, int n_in,
                              void* d_out, int out_size) {
    const float* feat     = (const float*)d_in[0];
    const float* ws0      = (const float*)d_in[1];
    const float* wn0      = (const float*)d_in[2];
    const float* ws1      = (const float*)d_in[3];
    const float* wn1      = (const float*)d_in[4];
    const float* wout     = (const float*)d_in[5];
    const float* bout     = (const float*)d_in[6];
    const int*   node_ids = (const int*)d_in[7];
    const int*   adj      = (const int*)d_in[8];
    float* out = (float*)d_out;
    (void)in_sizes; (void)n_in; (void)out_size;

    uint32_t f0a, f0b, f1a, f1b, l0a, l0b, l1a, l1b;
    tf2x32(0u, 42u, 0u, 0u, f0a, f0b);
    tf2x32(0u, 42u, 0u, 1u, f1a, f1b);
    tf2x32(f0a, f0b, 0u, 1u, l0a, l0b);
    tf2x32(f1a, f1b, 0u, 1u, l1a, l1b);

    float *H1, *Mm1, *C1;
    cudaGetSymbolAddress((void**)&H1,  g_H1);
    cudaGetSymbolAddress((void**)&Mm1, g_M1);
    cudaGetSymbolAddress((void**)&C1,  g_C1);

    cudaFuncSetAttribute(k_gemm_mma,
                         cudaFuncAttributeMaxDynamicSharedMemorySize, G_SMEM);

    k_wT<<<dim3(32, 2), 256>>>(ws0, wn0);
    k_hop1<<<M1SZ / 4, 256>>>((const float4*)feat, adj, node_ids,
                              l0a, l0b, l1a, l1b);
    k_hop0mean<<<BATCH / 4, 256>>>((const float4*)feat, node_ids);
    k_gemm_mma<<<dim3(MEXT / BM, 2), 256, G_SMEM>>>(H1, Mm1, C1);
    k_tail<<<BATCH / RROWS, 256>>>(ws1, wn1, wout, bout, out);
}

// round 6
// speedup vs baseline: 2.0779x; 1.1715x over previous
#include <cuda_runtime.h>
#include <stdint.h>
#include <math.h>

#define FEAT     256
#define MAX_DEG  128
#define BATCH    1024
#define NS0      10
#define NS1      25
#define M1SZ     (BATCH * NS0)     /* 10240 */
#define MEXT     (M1SZ + BATCH)    /* 11264 */
#define RROWS    4
#define BM       64
#define HOP1_BLKS (M1SZ / 4)       /* 2560 */

// ---------------- scratch ----------------
__device__ float g_H1[MEXT * FEAT];
__device__ float g_M1[MEXT * FEAT];
__device__ float g_C1[MEXT * FEAT];
__device__ float g_WT[2 * 128 * FEAT];

// ---------------- threefry2x32 ----------------
__host__ __device__ __forceinline__ uint32_t rotl32_(uint32_t x, int r) {
    return (x << r) | (x >> (32 - r));
}
__host__ __device__ inline void tf2x32(uint32_t k0, uint32_t k1,
                                       uint32_t x0, uint32_t x1,
                                       uint32_t &o0, uint32_t &o1) {
    uint32_t ks2 = k0 ^ k1 ^ 0x1BD11BDAu;
    x0 += k0; x1 += k1;
#define TFR(r) { x0 += x1; x1 = rotl32_(x1, (r)); x1 ^= x0; }
    TFR(13) TFR(15) TFR(26) TFR(6)
    x0 += k1;  x1 += ks2 + 1u;
    TFR(17) TFR(29) TFR(16) TFR(24)
    x0 += ks2; x1 += k0 + 2u;
    TFR(13) TFR(15) TFR(26) TFR(6)
    x0 += k0;  x1 += k1 + 3u;
    TFR(17) TFR(29) TFR(16) TFR(24)
    x0 += k1;  x1 += ks2 + 4u;
    TFR(13) TFR(15) TFR(26) TFR(6)
    x0 += ks2; x1 += k0 + 5u;
#undef TFR
    o0 = x0; o1 = x1;
}
__device__ __forceinline__ int rnd_col(uint32_t k0, uint32_t k1, uint32_t t) {
    uint32_t a, b;
    tf2x32(k0, k1, 0u, t, a, b);
    return (int)((a ^ b) & (uint32_t)(MAX_DEG - 1));
}

// ---------------- helpers ----------------
__device__ __forceinline__ void mma_tf32(float c[4], const uint32_t a[4],
                                         const uint32_t b[2]) {
    asm volatile(
        "mma.sync.aligned.m16n8k8.row.col.f32.tf32.tf32.f32 "
        "{%0,%1,%2,%3}, {%4,%5,%6,%7}, {%8,%9}, {%0,%1,%2,%3};"
        : "+f"(c[0]), "+f"(c[1]), "+f"(c[2]), "+f"(c[3])
        : "r"(a[0]), "r"(a[1]), "r"(a[2]), "r"(a[3]), "r"(b[0]), "r"(b[1]));
}
__device__ __forceinline__ uint32_t smem_u32(const void* p) {
    return (uint32_t)__cvta_generic_to_shared(p);
}
__device__ __forceinline__ void cp16(uint32_t s, const void* g) {
    asm volatile("cp.async.cg.shared.global [%0], [%1], 16;" :: "r"(s), "l"(g));
}
#define CP_COMMIT() asm volatile("cp.async.commit_group;" ::: "memory")
#define CP_WAIT1()  asm volatile("cp.async.wait_group 1;" ::: "memory")

// ---------------- prep: hop1 sample+gather+mean  AND  weight transpose ----
__global__ void __launch_bounds__(256)
k_prep(const float4* __restrict__ feat4, const int* __restrict__ adj,
       const int* __restrict__ node_ids,
       const float* __restrict__ w0, const float* __restrict__ w1,
       uint32_t l0a, uint32_t l0b, uint32_t l1a, uint32_t l1b) {
    const int tid = threadIdx.x;
    if (blockIdx.x >= HOP1_BLKS) {
        // ---- weight transpose + tf32 rounding ----
        __shared__ float tile[32][33];
        const int wb = blockIdx.x - HOP1_BLKS;     // 0..63
        const int mat = wb >> 5;                   // 0..1
        const int sub = wb & 31;
        const float* W = mat ? w1 : w0;
        float* WT = g_WT + mat * (128 * FEAT);
        const int k0 = (sub >> 2) * 32;
        const int n0 = (sub & 3) * 32;
        const int c = tid & 31, rw = tid >> 5;
#pragma unroll
        for (int r = rw; r < 32; r += 8) {
            float v = W[(k0 + r) * 128 + n0 + c];
            asm("cvt.rna.tf32.f32 %0, %0;" : "+f"(v));
            tile[r][c] = v;
        }
        __syncthreads();
#pragma unroll
        for (int r = rw; r < 32; r += 8)
            WT[(n0 + r) * FEAT + k0 + c] = tile[c][r];
        return;
    }
    // ---- hop1 ----
    const int j0 = blockIdx.x * 4;
    __shared__ int s1sh[4];
    __shared__ int s2s[4][NS1];
    if (tid < 4) {
        int j = j0 + tid;
        int c0 = rnd_col(l0a, l0b, (uint32_t)j);
        s1sh[tid] = adj[node_ids[j / NS0] * MAX_DEG + c0];
    }
    __syncthreads();
    if (tid < 4 * NS1) {
        int lj = tid / NS1, s = tid - lj * NS1;
        int c1 = rnd_col(l1a, l1b, (uint32_t)((j0 + lj) * NS1 + s));
        s2s[lj][s] = adj[s1sh[lj] * MAX_DEG + c1];
    }
    __syncthreads();
    const int lj = tid >> 6, c = tid & 63;
    const int j = j0 + lj;
    float4* H14 = (float4*)g_H1;
    float4* M14 = (float4*)g_M1;
    H14[j * 64 + c] = feat4[s1sh[lj] * 64 + c];
    float ax = 0.f, ay = 0.f, az = 0.f, aw = 0.f;
#pragma unroll
    for (int s = 0; s < NS1; s++) {
        float4 v = feat4[s2s[lj][s] * 64 + c];
        ax += v.x; ay += v.y; az += v.z; aw += v.w;
    }
    const float inv = 1.0f / NS1;
    M14[j * 64 + c] = make_float4(ax * inv, ay * inv, az * inv, aw * inv);
}

// ---------------- batch rows: H0 gather + M0 = mean10(H1) -----------------
__global__ void __launch_bounds__(256)
k_hop0mean(const float4* __restrict__ feat4, const int* __restrict__ node_ids) {
    const int tid = threadIdx.x;
    const int lj = tid >> 6, c = tid & 63;
    const int i = blockIdx.x * 4 + lj;
    float4* H14 = (float4*)g_H1;
    float4* M14 = (float4*)g_M1;
    H14[(size_t)(M1SZ + i) * 64 + c] = feat4[(size_t)node_ids[i] * 64 + c];
    float ax = 0.f, ay = 0.f, az = 0.f, aw = 0.f;
#pragma unroll
    for (int s = 0; s < NS0; s++) {
        float4 v = H14[(size_t)(i * NS0 + s) * 64 + c];
        ax += v.x; ay += v.y; az += v.z; aw += v.w;
    }
    const float inv = 1.0f / NS0;
    M14[(size_t)(M1SZ + i) * 64 + c] = make_float4(ax * inv, ay * inv,
                                                   az * inv, aw * inv);
}

// ---------------- tf32 mma.sync GEMM, 3-stage cp.async pipeline ----------
#define SA(b, r, c) sm[(b) * 6912 + (r) * 36 + (c)]
#define SB(b, r, c) sm[(b) * 6912 + 2304 + (r) * 36 + (c)]
#define G_SMEM (3 * 6912 * 4)

__global__ void __launch_bounds__(256)
k_gemm_mma(const float* __restrict__ A0, const float* __restrict__ A1,
           float* __restrict__ C) {
    extern __shared__ float sm[];
    const int tid = threadIdx.x, lane = tid & 31, wid = tid >> 5;
    const int wr = wid & 1, wc = wid >> 1;
    const int m0 = blockIdx.x * BM;
    const float4* __restrict__ A4 = (const float4*)(blockIdx.y ? A1 : A0);
    const float4* __restrict__ B4 =
        (const float4*)(g_WT + blockIdx.y * (128 * FEAT));
    const int colOff = blockIdx.y * 128;

    float acc[2][4][4];
#pragma unroll
    for (int mt = 0; mt < 2; mt++)
#pragma unroll
        for (int nt = 0; nt < 4; nt++)
#pragma unroll
            for (int q = 0; q < 4; q++) acc[mt][nt][q] = 0.f;

    auto stage = [&](int cc, int b) {
#pragma unroll
        for (int u = 0; u < 2; u++) {
            int fid = u * 256 + tid;
            int row = fid >> 3, q = fid & 7;
            cp16(smem_u32(&SA(b, row, q * 4)),
                 &A4[(size_t)(m0 + row) * 64 + cc * 8 + q]);
        }
#pragma unroll
        for (int u = 0; u < 4; u++) {
            int fid = u * 256 + tid;
            int row = fid >> 3, q = fid & 7;
            cp16(smem_u32(&SB(b, row, q * 4)),
                 &B4[(size_t)row * 64 + cc * 8 + q]);
        }
        CP_COMMIT();
    };

    stage(0, 0);
    stage(1, 1);
    for (int cc = 0; cc < 8; cc++) {
        const int b = cc - (cc / 3) * 3;        // cc % 3
        CP_WAIT1();
        __syncthreads();
        if (cc < 6) stage(cc + 2, (cc + 2) - ((cc + 2) / 3) * 3);
#pragma unroll
        for (int ks = 0; ks < 4; ks++) {
            const int k8 = ks * 8;
            uint32_t af[2][4], bf[4][2];
#pragma unroll
            for (int mt = 0; mt < 2; mt++) {
                const int rb = wr * 32 + mt * 16;
                af[mt][0] = __float_as_uint(SA(b, rb + (lane >> 2), k8 + (lane & 3)));
                af[mt][1] = __float_as_uint(SA(b, rb + 8 + (lane >> 2), k8 + (lane & 3)));
                af[mt][2] = __float_as_uint(SA(b, rb + (lane >> 2), k8 + 4 + (lane & 3)));
                af[mt][3] = __float_as_uint(SA(b, rb + 8 + (lane >> 2), k8 + 4 + (lane & 3)));
            }
#pragma unroll
            for (int nt = 0; nt < 4; nt++) {
                const int nb = wc * 32 + nt * 8;
                bf[nt][0] = __float_as_uint(SB(b, nb + (lane >> 2), k8 + (lane & 3)));
                bf[nt][1] = __float_as_uint(SB(b, nb + (lane >> 2), k8 + 4 + (lane & 3)));
            }
#pragma unroll
            for (int mt = 0; mt < 2; mt++)
#pragma unroll
                for (int nt = 0; nt < 4; nt++)
                    mma_tf32(acc[mt][nt], af[mt], bf[nt]);
        }
        __syncthreads();
    }

#pragma unroll
    for (int mt = 0; mt < 2; mt++) {
        const int row0 = m0 + wr * 32 + mt * 16 + (lane >> 2);
#pragma unroll
        for (int nt = 0; nt < 4; nt++) {
            const int col0 = colOff + wc * 32 + nt * 8 + (lane & 3) * 2;
            float2 v0 = make_float2(fmaxf(acc[mt][nt][0], 0.f),
                                    fmaxf(acc[mt][nt][1], 0.f));
            float2 v1 = make_float2(fmaxf(acc[mt][nt][2], 0.f),
                                    fmaxf(acc[mt][nt][3], 0.f));
            *(float2*)&C[(size_t)row0 * FEAT + col0] = v0;
            *(float2*)&C[(size_t)(row0 + 8) * FEAT + col0] = v1;
        }
    }
}

// ---------------- tail: layer-1 GEMM (k-split over 512 thr) + norm + dot --
__global__ void __launch_bounds__(512)
k_tail(const float* __restrict__ ws1, const float* __restrict__ wn1,
       const float* __restrict__ w_out, const float* __restrict__ b_out,
       float* __restrict__ out) {
    __shared__ __align__(16) float As[2][RROWS][FEAT];   // 8 KB
    __shared__ float part[RROWS][256];                   // 4 KB
    __shared__ float red[8][2 * RROWS];
    __shared__ float fin[2 * RROWS];

    const int t   = threadIdx.x;
    const int kh  = t >> 8;        // k-half
    const int c   = t & 255;       // output column 0..255
    const int h   = c >> 7;        // matrix select
    const int col = c & 127;
    const int i0  = blockIdx.x * RROWS;

    // stage: threads with kh=0 stage rows 0..1, kh=1 stage rows 2..3
#pragma unroll
    for (int rr = 0; rr < 2; rr++) {
        const int r = kh * 2 + rr;
        As[0][r][c] = g_C1[(size_t)(M1SZ + i0 + r) * FEAT + c];
        float acc = 0.f;
#pragma unroll
        for (int s = 0; s < NS0; s++)
            acc += g_C1[(size_t)((i0 + r) * NS0 + s) * FEAT + c];
        As[1][r][c] = acc * (1.0f / NS0);
    }
    __syncthreads();

    const float* __restrict__ W1 = h ? wn1 : ws1;
    const int kbase = kh * 128;
    float accB[RROWS];
#pragma unroll
    for (int r = 0; r < RROWS; r++) accB[r] = 0.f;
#pragma unroll 4
    for (int kk = 0; kk < 128; kk += 4) {
        const int k = kbase + kk;
        float w0 = W1[(k + 0) * 128 + col];
        float w1 = W1[(k + 1) * 128 + col];
        float w2 = W1[(k + 2) * 128 + col];
        float w3 = W1[(k + 3) * 128 + col];
#pragma unroll
        for (int r = 0; r < RROWS; r++) {
            const float4 a = *reinterpret_cast<const float4*>(&As[h][r][k]);
            accB[r] = fmaf(a.x, w0, accB[r]);
            accB[r] = fmaf(a.y, w1, accB[r]);
            accB[r] = fmaf(a.z, w2, accB[r]);
            accB[r] = fmaf(a.w, w3, accB[r]);
        }
    }

    if (kh == 1) {
#pragma unroll
        for (int r = 0; r < RROWS; r++) part[r][c] = accB[r];
    }
    __syncthreads();

    float ss[RROWS], dv[RROWS];
    if (kh == 0) {
        const float wo = w_out[c];
#pragma unroll
        for (int r = 0; r < RROWS; r++) {
            const float hv = fmaxf(accB[r] + part[r][c], 0.f);
            ss[r] = hv * hv;
            dv[r] = hv * wo;
        }
#pragma unroll
        for (int off = 16; off > 0; off >>= 1) {
#pragma unroll
            for (int r = 0; r < RROWS; r++) {
                ss[r] += __shfl_down_sync(0xffffffffu, ss[r], off);
                dv[r] += __shfl_down_sync(0xffffffffu, dv[r], off);
            }
        }
        const int lane = t & 31, wid = t >> 5;   // wid 0..7 for kh==0
        if (lane == 0) {
#pragma unroll
            for (int r = 0; r < RROWS; r++) {
                red[wid][r]         = ss[r];
                red[wid][RROWS + r] = dv[r];
            }
        }
    }
    __syncthreads();
    if (t < 2 * RROWS) {
        float v = 0.f;
#pragma unroll
        for (int w = 0; w < 8; w++) v += red[w][t];
        fin[t] = v;
    }
    __syncthreads();
    if (t < RROWS)
        out[i0 + t] = fin[RROWS + t] / sqrtf(fmaxf(fin[t], 1e-12f)) + b_out[0];
}

// ---------------- launch ----------------
extern "C" void kernel_launch(void* const* d_in, const int* in_sizes, int n_in,
                              void* d_out, int out_size) {
    const float* feat     = (const float*)d_in[0];
    const float* ws0      = (const float*)d_in[1];
    const float* wn0      = (const float*)d_in[2];
    const float* ws1      = (const float*)d_in[3];
    const float* wn1      = (const float*)d_in[4];
    const float* wout     = (const float*)d_in[5];
    const float* bout     = (const float*)d_in[6];
    const int*   node_ids = (const int*)d_in[7];
    const int*   adj      = (const int*)d_in[8];
    float* out = (float*)d_out;
    (void)in_sizes; (void)n_in; (void)out_size;

    uint32_t f0a, f0b, f1a, f1b, l0a, l0b, l1a, l1b;
    tf2x32(0u, 42u, 0u, 0u, f0a, f0b);
    tf2x32(0u, 42u, 0u, 1u, f1a, f1b);
    tf2x32(f0a, f0b, 0u, 1u, l0a, l0b);
    tf2x32(f1a, f1b, 0u, 1u, l1a, l1b);

    float *H1, *Mm1, *C1;
    cudaGetSymbolAddress((void**)&H1,  g_H1);
    cudaGetSymbolAddress((void**)&Mm1, g_M1);
    cudaGetSymbolAddress((void**)&C1,  g_C1);

    cudaFuncSetAttribute(k_gemm_mma,
                         cudaFuncAttributeMaxDynamicSharedMemorySize, G_SMEM);

    k_prep<<<HOP1_BLKS + 64, 256>>>((const float4*)feat, adj, node_ids,
                                    ws0, wn0, l0a, l0b, l1a, l1b);
    k_hop0mean<<<BATCH / 4, 256>>>((const float4*)feat, node_ids);
    k_gemm_mma<<<dim3(MEXT / BM, 2), 256, G_SMEM>>>(H1, Mm1, C1);
    k_tail<<<BATCH / RROWS, 512>>>(ws1, wn1, wout, bout, out);
}

// round 7
// speedup vs baseline: 2.1120x; 1.0164x over previous
#include <cuda_runtime.h>
#include <stdint.h>
#include <math.h>

#define FEAT     256
#define MAX_DEG  128
#define BATCH    1024
#define NS0      10
#define NS1      25
#define M1SZ     (BATCH * NS0)     /* 10240 */
#define MEXT     (M1SZ + BATCH)    /* 11264 */
#define BM       64
#define HOP1_BLKS (M1SZ / 4)       /* 2560 */
#define WMAT     (128 * FEAT)      /* floats per K-major weight matrix */

// ---------------- scratch ----------------
__device__ float g_H1[MEXT * FEAT];
__device__ float g_M1[MEXT * FEAT];      // ext region reused for meanC1
__device__ float g_C1[MEXT * FEAT];      // rows M1SZ.. are C0
__device__ float g_WT[4 * WMAT];         // ws0,wn0,ws1,wn1 K-major tf32
__device__ float g_HF[BATCH * FEAT];

// ---------------- threefry2x32 ----------------
__host__ __device__ __forceinline__ uint32_t rotl32_(uint32_t x, int r) {
    return (x << r) | (x >> (32 - r));
}
__host__ __device__ inline void tf2x32(uint32_t k0, uint32_t k1,
                                       uint32_t x0, uint32_t x1,
                                       uint32_t &o0, uint32_t &o1) {
    uint32_t ks2 = k0 ^ k1 ^ 0x1BD11BDAu;
    x0 += k0; x1 += k1;
#define TFR(r) { x0 += x1; x1 = rotl32_(x1, (r)); x1 ^= x0; }
    TFR(13) TFR(15) TFR(26) TFR(6)
    x0 += k1;  x1 += ks2 + 1u;
    TFR(17) TFR(29) TFR(16) TFR(24)
    x0 += ks2; x1 += k0 + 2u;
    TFR(13) TFR(15) TFR(26) TFR(6)
    x0 += k0;  x1 += k1 + 3u;
    TFR(17) TFR(29) TFR(16) TFR(24)
    x0 += k1;  x1 += ks2 + 4u;
    TFR(13) TFR(15) TFR(26) TFR(6)
    x0 += ks2; x1 += k0 + 5u;
#undef TFR
    o0 = x0; o1 = x1;
}
__device__ __forceinline__ int rnd_col(uint32_t k0, uint32_t k1, uint32_t t) {
    uint32_t a, b;
    tf2x32(k0, k1, 0u, t, a, b);
    return (int)((a ^ b) & (uint32_t)(MAX_DEG - 1));
}

// ---------------- helpers ----------------
__device__ __forceinline__ void mma_tf32(float c[4], const uint32_t a[4],
                                         const uint32_t b[2]) {
    asm volatile(
        "mma.sync.aligned.m16n8k8.row.col.f32.tf32.tf32.f32 "
        "{%0,%1,%2,%3}, {%4,%5,%6,%7}, {%8,%9}, {%0,%1,%2,%3};"
        : "+f"(c[0]), "+f"(c[1]), "+f"(c[2]), "+f"(c[3])
        : "r"(a[0]), "r"(a[1]), "r"(a[2]), "r"(a[3]), "r"(b[0]), "r"(b[1]));
}
__device__ __forceinline__ uint32_t smem_u32(const void* p) {
    return (uint32_t)__cvta_generic_to_shared(p);
}
__device__ __forceinline__ void cp16(uint32_t s, const void* g) {
    asm volatile("cp.async.cg.shared.global [%0], [%1], 16;" :: "r"(s), "l"(g));
}
#define CP_COMMIT() asm volatile("cp.async.commit_group;" ::: "memory")
#define CP_WAIT1()  asm volatile("cp.async.wait_group 1;" ::: "memory")

// ---------------- prep: hop1 sample+gather+mean AND weight transposes -----
__global__ void __launch_bounds__(256)
k_prep(const float4* __restrict__ feat4, const int* __restrict__ adj,
       const int* __restrict__ node_ids,
       const float* __restrict__ w0, const float* __restrict__ w1,
       const float* __restrict__ w2, const float* __restrict__ w3,
       uint32_t l0a, uint32_t l0b, uint32_t l1a, uint32_t l1b) {
    const int tid = threadIdx.x;
    if (blockIdx.x >= HOP1_BLKS) {
        __shared__ float tile[32][33];
        const int wb = blockIdx.x - HOP1_BLKS;     // 0..127
        const int mat = wb >> 5;                   // 0..3
        const int sub = wb & 31;
        const float* W = (mat == 0) ? w0 : (mat == 1) ? w1 : (mat == 2) ? w2 : w3;
        float* WT = g_WT + mat * WMAT;
        const int k0 = (sub >> 2) * 32;
        const int n0 = (sub & 3) * 32;
        const int c = tid & 31, rw = tid >> 5;
#pragma unroll
        for (int r = rw; r < 32; r += 8) {
            float v = W[(k0 + r) * 128 + n0 + c];
            asm("cvt.rna.tf32.f32 %0, %0;" : "+f"(v));
            tile[r][c] = v;
        }
        __syncthreads();
#pragma unroll
        for (int r = rw; r < 32; r += 8)
            WT[(n0 + r) * FEAT + k0 + c] = tile[c][r];
        return;
    }
    const int j0 = blockIdx.x * 4;
    __shared__ int s1sh[4];
    __shared__ int s2s[4][NS1];
    if (tid < 4) {
        int j = j0 + tid;
        int c0 = rnd_col(l0a, l0b, (uint32_t)j);
        s1sh[tid] = adj[node_ids[j / NS0] * MAX_DEG + c0];
    }
    __syncthreads();
    if (tid < 4 * NS1) {
        int lj = tid / NS1, s = tid - lj * NS1;
        int c1 = rnd_col(l1a, l1b, (uint32_t)((j0 + lj) * NS1 + s));
        s2s[lj][s] = adj[s1sh[lj] * MAX_DEG + c1];
    }
    __syncthreads();
    const int lj = tid >> 6, c = tid & 63;
    const int j = j0 + lj;
    float4* H14 = (float4*)g_H1;
    float4* M14 = (float4*)g_M1;
    H14[j * 64 + c] = feat4[s1sh[lj] * 64 + c];
    float ax = 0.f, ay = 0.f, az = 0.f, aw = 0.f;
#pragma unroll
    for (int s = 0; s < NS1; s++) {
        float4 v = feat4[s2s[lj][s] * 64 + c];
        ax += v.x; ay += v.y; az += v.z; aw += v.w;
    }
    const float inv = 1.0f / NS1;
    M14[j * 64 + c] = make_float4(ax * inv, ay * inv, az * inv, aw * inv);
}

// ---------------- batch rows: H0 gather + M0 = mean10(H1) -----------------
__global__ void __launch_bounds__(256)
k_hop0mean(const float4* __restrict__ feat4, const int* __restrict__ node_ids) {
    const int tid = threadIdx.x;
    const int lj = tid >> 6, c = tid & 63;
    const int i = blockIdx.x * 4 + lj;
    float4* H14 = (float4*)g_H1;
    float4* M14 = (float4*)g_M1;
    H14[(size_t)(M1SZ + i) * 64 + c] = feat4[(size_t)node_ids[i] * 64 + c];
    float ax = 0.f, ay = 0.f, az = 0.f, aw = 0.f;
#pragma unroll
    for (int s = 0; s < NS0; s++) {
        float4 v = H14[(size_t)(i * NS0 + s) * 64 + c];
        ax += v.x; ay += v.y; az += v.z; aw += v.w;
    }
    const float inv = 1.0f / NS0;
    M14[(size_t)(M1SZ + i) * 64 + c] = make_float4(ax * inv, ay * inv,
                                                   az * inv, aw * inv);
}

// ---------------- meanC1 -> g_M1 ext region ----------------
__global__ void __launch_bounds__(256)
k_mid() {
    const int tid = threadIdx.x;
    const int lj = tid >> 6, c = tid & 63;
    const int i = blockIdx.x * 4 + lj;
    const float4* C14 = (const float4*)g_C1;
    float4* M14 = (float4*)g_M1;
    float ax = 0.f, ay = 0.f, az = 0.f, aw = 0.f;
#pragma unroll
    for (int s = 0; s < NS0; s++) {
        float4 v = C14[(size_t)(i * NS0 + s) * 64 + c];
        ax += v.x; ay += v.y; az += v.z; aw += v.w;
    }
    const float inv = 1.0f / NS0;
    M14[(size_t)(M1SZ + i) * 64 + c] = make_float4(ax * inv, ay * inv,
                                                   az * inv, aw * inv);
}

// ---------------- tf32 mma.sync GEMM, 3-stage cp.async pipeline ----------
// C[:,half*128..] = relu(Ahalf @ W[half]); W = two K-major mats at Wbase.
#define SA(b, r, c) sm[(b) * 6912 + (r) * 36 + (c)]
#define SB(b, r, c) sm[(b) * 6912 + 2304 + (r) * 36 + (c)]
#define G_SMEM (3 * 6912 * 4)

__global__ void __launch_bounds__(256)
k_gemm_mma(const float* __restrict__ A0, const float* __restrict__ A1,
           const float* __restrict__ Wbase, float* __restrict__ C) {
    extern __shared__ float sm[];
    const int tid = threadIdx.x, lane = tid & 31, wid = tid >> 5;
    const int wr = wid & 1, wc = wid >> 1;
    const int m0 = blockIdx.x * BM;
    const float4* __restrict__ A4 = (const float4*)(blockIdx.y ? A1 : A0);
    const float4* __restrict__ B4 =
        (const float4*)(Wbase + blockIdx.y * WMAT);
    const int colOff = blockIdx.y * 128;

    float acc[2][4][4];
#pragma unroll
    for (int mt = 0; mt < 2; mt++)
#pragma unroll
        for (int nt = 0; nt < 4; nt++)
#pragma unroll
            for (int q = 0; q < 4; q++) acc[mt][nt][q] = 0.f;

    auto stage = [&](int cc, int b) {
#pragma unroll
        for (int u = 0; u < 2; u++) {
            int fid = u * 256 + tid;
            int row = fid >> 3, q = fid & 7;
            cp16(smem_u32(&SA(b, row, q * 4)),
                 &A4[(size_t)(m0 + row) * 64 + cc * 8 + q]);
        }
#pragma unroll
        for (int u = 0; u < 4; u++) {
            int fid = u * 256 + tid;
            int row = fid >> 3, q = fid & 7;
            cp16(smem_u32(&SB(b, row, q * 4)),
                 &B4[(size_t)row * 64 + cc * 8 + q]);
        }
        CP_COMMIT();
    };

    stage(0, 0);
    stage(1, 1);
    for (int cc = 0; cc < 8; cc++) {
        const int b = cc - (cc / 3) * 3;
        CP_WAIT1();
        __syncthreads();
        if (cc < 6) stage(cc + 2, (cc + 2) - ((cc + 2) / 3) * 3);
#pragma unroll
        for (int ks = 0; ks < 4; ks++) {
            const int k8 = ks * 8;
            uint32_t af[2][4], bf[4][2];
#pragma unroll
            for (int mt = 0; mt < 2; mt++) {
                const int rb = wr * 32 + mt * 16;
                af[mt][0] = __float_as_uint(SA(b, rb + (lane >> 2), k8 + (lane & 3)));
                af[mt][1] = __float_as_uint(SA(b, rb + 8 + (lane >> 2), k8 + (lane & 3)));
                af[mt][2] = __float_as_uint(SA(b, rb + (lane >> 2), k8 + 4 + (lane & 3)));
                af[mt][3] = __float_as_uint(SA(b, rb + 8 + (lane >> 2), k8 + 4 + (lane & 3)));
            }
#pragma unroll
            for (int nt = 0; nt < 4; nt++) {
                const int nb = wc * 32 + nt * 8;
                bf[nt][0] = __float_as_uint(SB(b, nb + (lane >> 2), k8 + (lane & 3)));
                bf[nt][1] = __float_as_uint(SB(b, nb + (lane >> 2), k8 + 4 + (lane & 3)));
            }
#pragma unroll
            for (int mt = 0; mt < 2; mt++)
#pragma unroll
                for (int nt = 0; nt < 4; nt++)
                    mma_tf32(acc[mt][nt], af[mt], bf[nt]);
        }
        __syncthreads();
    }

#pragma unroll
    for (int mt = 0; mt < 2; mt++) {
        const int row0 = m0 + wr * 32 + mt * 16 + (lane >> 2);
#pragma unroll
        for (int nt = 0; nt < 4; nt++) {
            const int col0 = colOff + wc * 32 + nt * 8 + (lane & 3) * 2;
            float2 v0 = make_float2(fmaxf(acc[mt][nt][0], 0.f),
                                    fmaxf(acc[mt][nt][1], 0.f));
            float2 v1 = make_float2(fmaxf(acc[mt][nt][2], 0.f),
                                    fmaxf(acc[mt][nt][3], 0.f));
            *(float2*)&C[(size_t)row0 * FEAT + col0] = v0;
            *(float2*)&C[(size_t)(row0 + 8) * FEAT + col0] = v1;
        }
    }
}

// ---------------- final: l2-normalize rows of HF, dot w_out, bias ---------
#define FROWS 8
__global__ void __launch_bounds__(256)
k_final(const float* __restrict__ w_out, const float* __restrict__ b_out,
        float* __restrict__ out) {
    __shared__ float red[8][2 * FROWS];
    __shared__ float fin[2 * FROWS];
    const int t = threadIdx.x;
    const int i0 = blockIdx.x * FROWS;
    const float wo = w_out[t];
    float ss[FROWS], dv[FROWS];
#pragma unroll
    for (int r = 0; r < FROWS; r++) {
        const float hv = g_HF[(size_t)(i0 + r) * FEAT + t];
        ss[r] = hv * hv;
        dv[r] = hv * wo;
    }
#pragma unroll
    for (int off = 16; off > 0; off >>= 1) {
#pragma unroll
        for (int r = 0; r < FROWS; r++) {
            ss[r] += __shfl_down_sync(0xffffffffu, ss[r], off);
            dv[r] += __shfl_down_sync(0xffffffffu, dv[r], off);
        }
    }
    const int lane = t & 31, wid = t >> 5;
    if (lane == 0) {
#pragma unroll
        for (int r = 0; r < FROWS; r++) {
            red[wid][r]         = ss[r];
            red[wid][FROWS + r] = dv[r];
        }
    }
    __syncthreads();
    if (t < 2 * FROWS) {
        float v = 0.f;
#pragma unroll
        for (int w = 0; w < 8; w++) v += red[w][t];
        fin[t] = v;
    }
    __syncthreads();
    if (t < FROWS)
        out[i0 + t] = fin[FROWS + t] / sqrtf(fmaxf(fin[t], 1e-12f)) + b_out[0];
}

// ---------------- launch ----------------
extern "C" void kernel_launch(void* const* d_in, const int* in_sizes, int n_in,
                              void* d_out, int out_size) {
    const float* feat     = (const float*)d_in[0];
    const float* ws0      = (const float*)d_in[1];
    const float* wn0      = (const float*)d_in[2];
    const float* ws1      = (const float*)d_in[3];
    const float* wn1      = (const float*)d_in[4];
    const float* wout     = (const float*)d_in[5];
    const float* bout     = (const float*)d_in[6];
    const int*   node_ids = (const int*)d_in[7];
    const int*   adj      = (const int*)d_in[8];
    float* out = (float*)d_out;
    (void)in_sizes; (void)n_in; (void)out_size;

    uint32_t f0a, f0b, f1a, f1b, l0a, l0b, l1a, l1b;
    tf2x32(0u, 42u, 0u, 0u, f0a, f0b);
    tf2x32(0u, 42u, 0u, 1u, f1a, f1b);
    tf2x32(f0a, f0b, 0u, 1u, l0a, l0b);
    tf2x32(f1a, f1b, 0u, 1u, l1a, l1b);

    float *H1, *Mm1, *C1, *WT, *HF;
    cudaGetSymbolAddress((void**)&H1,  g_H1);
    cudaGetSymbolAddress((void**)&Mm1, g_M1);
    cudaGetSymbolAddress((void**)&C1,  g_C1);
    cudaGetSymbolAddress((void**)&WT,  g_WT);
    cudaGetSymbolAddress((void**)&HF,  g_HF);

    cudaFuncSetAttribute(k_gemm_mma,
                         cudaFuncAttributeMaxDynamicSharedMemorySize, G_SMEM);

    k_prep<<<HOP1_BLKS + 128, 256>>>((const float4*)feat, adj, node_ids,
                                     ws0, wn0, ws1, wn1,
                                     l0a, l0b, l1a, l1b);
    k_hop0mean<<<BATCH / 4, 256>>>((const float4*)feat, node_ids);
    k_gemm_mma<<<dim3(MEXT / BM, 2), 256, G_SMEM>>>(H1, Mm1, WT, C1);
    k_mid<<<BATCH / 4, 256>>>();
    k_gemm_mma<<<dim3(BATCH / BM, 2), 256, G_SMEM>>>(C1 + (size_t)M1SZ * FEAT,
                                                     Mm1 + (size_t)M1SZ * FEAT,
                                                     WT + 2 * WMAT, HF);
    k_final<<<BATCH / FROWS, 256>>>(wout, bout, out);
}

// round 8
// speedup vs baseline: 2.1794x; 1.0319x over previous
#include <cuda_runtime.h>
#include <stdint.h>
#include <math.h>

#define FEAT     256
#define MAX_DEG  128
#define BATCH    1024
#define NS0      10
#define NS1      25
#define M1SZ     (BATCH * NS0)     /* 10240 */
#define MEXT     (M1SZ + BATCH)    /* 11264 */
#define BM       64
#define HOP1_BLKS (M1SZ / 4)       /* 2560 */
#define WT_BLKS   128
#define HOP0_BLKS (BATCH / 4)      /* 256 */
#define WMAT     (128 * FEAT)
#define G2_BLOCKS 32               /* gemm2 grid = (16,2) */

// ---------------- scratch ----------------
__device__ float g_H1[MEXT * FEAT];
__device__ float g_M1[MEXT * FEAT];
__device__ float g_C1[MEXT * FEAT];
__device__ float g_WT[4 * WMAT];
__device__ float g_SS[BATCH];
__device__ float g_DV[BATCH];
__device__ unsigned int g_done = 0;

// ---------------- threefry2x32 ----------------
__host__ __device__ __forceinline__ uint32_t rotl32_(uint32_t x, int r) {
    return (x << r) | (x >> (32 - r));
}
__host__ __device__ inline void tf2x32(uint32_t k0, uint32_t k1,
                                       uint32_t x0, uint32_t x1,
                                       uint32_t &o0, uint32_t &o1) {
    uint32_t ks2 = k0 ^ k1 ^ 0x1BD11BDAu;
    x0 += k0; x1 += k1;
#define TFR(r) { x0 += x1; x1 = rotl32_(x1, (r)); x1 ^= x0; }
    TFR(13) TFR(15) TFR(26) TFR(6)
    x0 += k1;  x1 += ks2 + 1u;
    TFR(17) TFR(29) TFR(16) TFR(24)
    x0 += ks2; x1 += k0 + 2u;
    TFR(13) TFR(15) TFR(26) TFR(6)
    x0 += k0;  x1 += k1 + 3u;
    TFR(17) TFR(29) TFR(16) TFR(24)
    x0 += k1;  x1 += ks2 + 4u;
    TFR(13) TFR(15) TFR(26) TFR(6)
    x0 += ks2; x1 += k0 + 5u;
#undef TFR
    o0 = x0; o1 = x1;
}
__device__ __forceinline__ int rnd_col(uint32_t k0, uint32_t k1, uint32_t t) {
    uint32_t a, b;
    tf2x32(k0, k1, 0u, t, a, b);
    return (int)((a ^ b) & (uint32_t)(MAX_DEG - 1));
}

// ---------------- helpers ----------------
__device__ __forceinline__ void mma_tf32(float c[4], const uint32_t a[4],
                                         const uint32_t b[2]) {
    asm volatile(
        "mma.sync.aligned.m16n8k8.row.col.f32.tf32.tf32.f32 "
        "{%0,%1,%2,%3}, {%4,%5,%6,%7}, {%8,%9}, {%0,%1,%2,%3};"
        : "+f"(c[0]), "+f"(c[1]), "+f"(c[2]), "+f"(c[3])
        : "r"(a[0]), "r"(a[1]), "r"(a[2]), "r"(a[3]), "r"(b[0]), "r"(b[1]));
}
__device__ __forceinline__ uint32_t smem_u32(const void* p) {
    return (uint32_t)__cvta_generic_to_shared(p);
}
__device__ __forceinline__ void cp16(uint32_t s, const void* g) {
    asm volatile("cp.async.cg.shared.global [%0], [%1], 16;" :: "r"(s), "l"(g));
}
#define CP_COMMIT() asm volatile("cp.async.commit_group;" ::: "memory")
#define CP_WAIT1()  asm volatile("cp.async.wait_group 1;" ::: "memory")

// ---------------- prep: hop1 + weight transposes + hop0 (independent) -----
__global__ void __launch_bounds__(256)
k_prep(const float4* __restrict__ feat4, const int* __restrict__ adj,
       const int* __restrict__ node_ids,
       const float* __restrict__ w0, const float* __restrict__ w1,
       const float* __restrict__ w2, const float* __restrict__ w3,
       uint32_t l0a, uint32_t l0b, uint32_t l1a, uint32_t l1b) {
    const int tid = threadIdx.x;
    float4* H14 = (float4*)g_H1;
    float4* M14 = (float4*)g_M1;

    if (blockIdx.x >= HOP1_BLKS + WT_BLKS) {
        // ---- hop0: H0 gather + M0 = mean10(features[s1]) (recompute s1) ----
        __shared__ int s1g[40];
        const int i0 = (blockIdx.x - HOP1_BLKS - WT_BLKS) * 4;  // batch base
        if (tid < 40) {
            const int j = i0 * NS0 + tid;
            int c0 = rnd_col(l0a, l0b, (uint32_t)j);
            s1g[tid] = adj[node_ids[j / NS0] * MAX_DEG + c0];
        }
        __syncthreads();
        const int lj = tid >> 6, c = tid & 63;
        const int i = i0 + lj;
        H14[(size_t)(M1SZ + i) * 64 + c] = feat4[(size_t)node_ids[i] * 64 + c];
        float ax = 0.f, ay = 0.f, az = 0.f, aw = 0.f;
#pragma unroll
        for (int s = 0; s < NS0; s++) {
            float4 v = feat4[(size_t)s1g[lj * NS0 + s] * 64 + c];
            ax += v.x; ay += v.y; az += v.z; aw += v.w;
        }
        const float inv = 1.0f / NS0;
        M14[(size_t)(M1SZ + i) * 64 + c] = make_float4(ax * inv, ay * inv,
                                                       az * inv, aw * inv);
        return;
    }
    if (blockIdx.x >= HOP1_BLKS) {
        // ---- weight transpose + tf32 rounding ----
        __shared__ float tile[32][33];
        const int wb = blockIdx.x - HOP1_BLKS;
        const int mat = wb >> 5;
        const int sub = wb & 31;
        const float* W = (mat == 0) ? w0 : (mat == 1) ? w1 : (mat == 2) ? w2 : w3;
        float* WT = g_WT + mat * WMAT;
        const int k0 = (sub >> 2) * 32;
        const int n0 = (sub & 3) * 32;
        const int c = tid & 31, rw = tid >> 5;
#pragma unroll
        for (int r = rw; r < 32; r += 8) {
            float v = W[(k0 + r) * 128 + n0 + c];
            asm("cvt.rna.tf32.f32 %0, %0;" : "+f"(v));
            tile[r][c] = v;
        }
        __syncthreads();
#pragma unroll
        for (int r = rw; r < 32; r += 8)
            WT[(n0 + r) * FEAT + k0 + c] = tile[c][r];
        return;
    }
    // ---- hop1: sample + gather + mean25 ----
    const int j0 = blockIdx.x * 4;
    __shared__ int s1sh[4];
    __shared__ int s2s[4][NS1];
    if (tid < 4) {
        int j = j0 + tid;
        int c0 = rnd_col(l0a, l0b, (uint32_t)j);
        s1sh[tid] = adj[node_ids[j / NS0] * MAX_DEG + c0];
    }
    __syncthreads();
    if (tid < 4 * NS1) {
        int lj = tid / NS1, s = tid - lj * NS1;
        int c1 = rnd_col(l1a, l1b, (uint32_t)((j0 + lj) * NS1 + s));
        s2s[lj][s] = adj[s1sh[lj] * MAX_DEG + c1];
    }
    __syncthreads();
    const int lj = tid >> 6, c = tid & 63;
    const int j = j0 + lj;
    H14[j * 64 + c] = feat4[s1sh[lj] * 64 + c];
    float ax = 0.f, ay = 0.f, az = 0.f, aw = 0.f;
#pragma unroll
    for (int s = 0; s < NS1; s++) {
        float4 v = feat4[s2s[lj][s] * 64 + c];
        ax += v.x; ay += v.y; az += v.z; aw += v.w;
    }
    const float inv = 1.0f / NS1;
    M14[j * 64 + c] = make_float4(ax * inv, ay * inv, az * inv, aw * inv);
}

// ---------------- meanC1 (one row per block) + zero reduction buffers -----
__global__ void __launch_bounds__(128)
k_mid() {
    const int i = blockIdx.x;
    const int t = threadIdx.x;
    if (t == 0) { g_SS[i] = 0.f; g_DV[i] = 0.f; }
    const float2* C12 = (const float2*)g_C1;
    float2* M12 = (float2*)g_M1;
    float ax = 0.f, ay = 0.f;
#pragma unroll
    for (int s = 0; s < NS0; s++) {
        float2 v = C12[(size_t)(i * NS0 + s) * 128 + t];
        ax += v.x; ay += v.y;
    }
    const float inv = 1.0f / NS0;
    M12[(size_t)(M1SZ + i) * 128 + t] = make_float2(ax * inv, ay * inv);
}

// ---------------- tf32 mma.sync GEMM, 3-stage cp.async pipeline ----------
#define SA(b, r, c) sm[(b) * 6912 + (r) * 36 + (c)]
#define SB(b, r, c) sm[(b) * 6912 + 2304 + (r) * 36 + (c)]
#define G_SMEM (3 * 6912 * 4)

template<bool FUSE_OUT>
__global__ void __launch_bounds__(256)
k_gemm_mma(const float* __restrict__ A0, const float* __restrict__ A1,
           const float* __restrict__ Wbase, float* __restrict__ C,
           const float* __restrict__ w_out, const float* __restrict__ b_out,
           float* __restrict__ out) {
    extern __shared__ float sm[];
    const int tid = threadIdx.x, lane = tid & 31, wid = tid >> 5;
    const int wr = wid & 1, wc = wid >> 1;
    const int m0 = blockIdx.x * BM;
    const float4* __restrict__ A4 = (const float4*)(blockIdx.y ? A1 : A0);
    const float4* __restrict__ B4 =
        (const float4*)(Wbase + blockIdx.y * WMAT);
    const int colOff = blockIdx.y * 128;

    float acc[2][4][4];
#pragma unroll
    for (int mt = 0; mt < 2; mt++)
#pragma unroll
        for (int nt = 0; nt < 4; nt++)
#pragma unroll
            for (int q = 0; q < 4; q++) acc[mt][nt][q] = 0.f;

    auto stage = [&](int cc, int b) {
#pragma unroll
        for (int u = 0; u < 2; u++) {
            int fid = u * 256 + tid;
            int row = fid >> 3, q = fid & 7;
            cp16(smem_u32(&SA(b, row, q * 4)),
                 &A4[(size_t)(m0 + row) * 64 + cc * 8 + q]);
        }
#pragma unroll
        for (int u = 0; u < 4; u++) {
            int fid = u * 256 + tid;
            int row = fid >> 3, q = fid & 7;
            cp16(smem_u32(&SB(b, row, q * 4)),
                 &B4[(size_t)row * 64 + cc * 8 + q]);
        }
        CP_COMMIT();
    };

    stage(0, 0);
    stage(1, 1);
    for (int cc = 0; cc < 8; cc++) {
        const int b = cc - (cc / 3) * 3;
        CP_WAIT1();
        __syncthreads();
        if (cc < 6) stage(cc + 2, (cc + 2) - ((cc + 2) / 3) * 3);
#pragma unroll
        for (int ks = 0; ks < 4; ks++) {
            const int k8 = ks * 8;
            uint32_t af[2][4], bf[4][2];
#pragma unroll
            for (int mt = 0; mt < 2; mt++) {
                const int rb = wr * 32 + mt * 16;
                af[mt][0] = __float_as_uint(SA(b, rb + (lane >> 2), k8 + (lane & 3)));
                af[mt][1] = __float_as_uint(SA(b, rb + 8 + (lane >> 2), k8 + (lane & 3)));
                af[mt][2] = __float_as_uint(SA(b, rb + (lane >> 2), k8 + 4 + (lane & 3)));
                af[mt][3] = __float_as_uint(SA(b, rb + 8 + (lane >> 2), k8 + 4 + (lane & 3)));
            }
#pragma unroll
            for (int nt = 0; nt < 4; nt++) {
                const int nb = wc * 32 + nt * 8;
                bf[nt][0] = __float_as_uint(SB(b, nb + (lane >> 2), k8 + (lane & 3)));
                bf[nt][1] = __float_as_uint(SB(b, nb + (lane >> 2), k8 + 4 + (lane & 3)));
            }
#pragma unroll
            for (int mt = 0; mt < 2; mt++)
#pragma unroll
                for (int nt = 0; nt < 4; nt++)
                    mma_tf32(acc[mt][nt], af[mt], bf[nt]);
        }
        __syncthreads();
    }

    if (!FUSE_OUT) {
#pragma unroll
        for (int mt = 0; mt < 2; mt++) {
            const int row0 = m0 + wr * 32 + mt * 16 + (lane >> 2);
#pragma unroll
            for (int nt = 0; nt < 4; nt++) {
                const int col0 = colOff + wc * 32 + nt * 8 + (lane & 3) * 2;
                float2 v0 = make_float2(fmaxf(acc[mt][nt][0], 0.f),
                                        fmaxf(acc[mt][nt][1], 0.f));
                float2 v1 = make_float2(fmaxf(acc[mt][nt][2], 0.f),
                                        fmaxf(acc[mt][nt][3], 0.f));
                *(float2*)&C[(size_t)row0 * FEAT + col0] = v0;
                *(float2*)&C[(size_t)(row0 + 8) * FEAT + col0] = v1;
            }
        }
        return;
    }

    // ---- fused epilogue: per-row sum(h^2), sum(h*w_out) over this tile ----
    float* ssm = sm;          // [64]
    float* dvm = sm + 64;     // [64]
    if (tid < 64) { ssm[tid] = 0.f; dvm[tid] = 0.f; }
    __syncthreads();

#pragma unroll
    for (int mt = 0; mt < 2; mt++) {
#pragma unroll
        for (int pair = 0; pair < 2; pair++) {
            const int lr = wr * 32 + mt * 16 + pair * 8 + (lane >> 2);
            float ss = 0.f, dv = 0.f;
#pragma unroll
            for (int nt = 0; nt < 4; nt++) {
                const int col0 = colOff + wc * 32 + nt * 8 + (lane & 3) * 2;
                const float h0 = fmaxf(acc[mt][nt][pair * 2 + 0], 0.f);
                const float h1 = fmaxf(acc[mt][nt][pair * 2 + 1], 0.f);
                ss += h0 * h0 + h1 * h1;
                dv += h0 * w_out[col0] + h1 * w_out[col0 + 1];
            }
            // reduce over lane&3 (the 4 lanes sharing this row in this warp)
            ss += __shfl_xor_sync(0xffffffffu, ss, 1);
            ss += __shfl_xor_sync(0xffffffffu, ss, 2);
            dv += __shfl_xor_sync(0xffffffffu, dv, 1);
            dv += __shfl_xor_sync(0xffffffffu, dv, 2);
            if ((lane & 3) == 0) {
                atomicAdd(&ssm[lr], ss);
                atomicAdd(&dvm[lr], dv);
            }
        }
    }
    __syncthreads();
    if (tid < 64) {
        atomicAdd(&g_SS[m0 + tid], ssm[tid]);
        atomicAdd(&g_DV[m0 + tid], dvm[tid]);
    }
    __threadfence();
    __shared__ unsigned int isLast;
    if (tid == 0) {
        unsigned int old = atomicAdd(&g_done, 1u);
        isLast = (old == G2_BLOCKS - 1) ? 1u : 0u;
    }
    __syncthreads();
    if (isLast) {
        __threadfence();
        if (tid == 0) g_done = 0u;
        const float bo = b_out[0];
#pragma unroll
        for (int r = tid; r < BATCH; r += 256) {
            float ss = g_SS[r], dv = g_DV[r];
            out[r] = dv / sqrtf(fmaxf(ss, 1e-12f)) + bo;
        }
    }
}

// ---------------- launch ----------------
extern "C" void kernel_launch(void* const* d_in, const int* in_sizes, int n_in,
                              void* d_out, int out_size) {
    const float* feat     = (const float*)d_in[0];
    const float* ws0      = (const float*)d_in[1];
    const float* wn0      = (const float*)d_in[2];
    const float* ws1      = (const float*)d_in[3];
    const float* wn1      = (const float*)d_in[4];
    const float* wout     = (const float*)d_in[5];
    const float* bout     = (const float*)d_in[6];
    const int*   node_ids = (const int*)d_in[7];
    const int*   adj      = (const int*)d_in[8];
    float* out = (float*)d_out;
    (void)in_sizes; (void)n_in; (void)out_size;

    uint32_t f0a, f0b, f1a, f1b, l0a, l0b, l1a, l1b;
    tf2x32(0u, 42u, 0u, 0u, f0a, f0b);
    tf2x32(0u, 42u, 0u, 1u, f1a, f1b);
    tf2x32(f0a, f0b, 0u, 1u, l0a, l0b);
    tf2x32(f1a, f1b, 0u, 1u, l1a, l1b);

    float *H1, *Mm1, *C1, *WT;
    cudaGetSymbolAddress((void**)&H1,  g_H1);
    cudaGetSymbolAddress((void**)&Mm1, g_M1);
    cudaGetSymbolAddress((void**)&C1,  g_C1);
    cudaGetSymbolAddress((void**)&WT,  g_WT);

    cudaFuncSetAttribute(k_gemm_mma<false>,
                         cudaFuncAttributeMaxDynamicSharedMemorySize, G_SMEM);
    cudaFuncSetAttribute(k_gemm_mma<true>,
                         cudaFuncAttributeMaxDynamicSharedMemorySize, G_SMEM);

    k_prep<<<HOP1_BLKS + WT_BLKS + HOP0_BLKS, 256>>>(
        (const float4*)feat, adj, node_ids, ws0, wn0, ws1, wn1,
        l0a, l0b, l1a, l1b);
    k_gemm_mma<false><<<dim3(MEXT / BM, 2), 256, G_SMEM>>>(
        H1, Mm1, WT, C1, nullptr, nullptr, nullptr);
    k_mid<<<BATCH, 128>>>();
    k_gemm_mma<true><<<dim3(BATCH / BM, 2), 256, G_SMEM>>>(
        C1 + (size_t)M1SZ * FEAT, Mm1 + (size_t)M1SZ * FEAT,
        WT + 2 * WMAT, nullptr, wout, bout, out);
}